// round 11
// baseline (speedup 1.0000x reference)
#include <cuda_runtime.h>
#include <cuda_fp16.h>
#include <math.h>

// ---------------- problem constants ----------------
#define NN    8192
#define EE    262144
#define HID   128
#define NRBF  50
#define K1    64
#define NLAY  6
#define PR    72           // smem pitch (fp16) for rbf / W1^T
#define PT    136          // smem pitch (fp16) for T / W2^T / F / node tiles
#define NSLOT 20

typedef __half  h16;
typedef __half2 h162;

// ---------------- device scratch ----------------
__device__ __align__(16) h16 g_rbf[(size_t)EE * K1];
__device__ __align__(16) h16 g_w1t_hi[NLAY * HID * K1];
__device__ __align__(16) h16 g_w1t_lo[NLAY * HID * K1];
__device__ __align__(16) h16 g_w2t_hi[NLAY * HID * HID];
__device__ __align__(16) h16 g_w2t_lo[NLAY * HID * HID];
__device__ __align__(16) h16 g_npt_hi[HID * K1];
__device__ __align__(16) h16 g_npt_lo[HID * K1];
__device__ __align__(16) h16 g_nwt_hi[NSLOT * HID * HID];
__device__ __align__(16) h16 g_nwt_lo[NSLOT * HID * HID];
__device__ float g_cut[EE];
__device__ float g_cutm[EE];
__device__ int   g_srow[EE];
__device__ int   g_sdst[EE];
__device__ int   g_perm[EE];
__device__ int   g_cnt[NN];
__device__ int   g_offm[NN];
__device__ float g_x  [NN * HID];
__device__ float g_h  [NN * HID];
__device__ float g_agg[NN * HID];
__device__ float g_nex[NN * HID];

// ---------------- small helper kernels ----------------
__global__ void k_zero_cnt() {
    int i = blockIdx.x * blockDim.x + threadIdx.x;
    if (i < NN) g_cnt[i] = 0;
}

__global__ void k_hist(const int* __restrict__ ei) {
    int e = blockIdx.x * blockDim.x + threadIdx.x;
    if (e < EE) atomicAdd(&g_cnt[ei[EE + e]], 1);
}

__global__ void k_scan() {
    __shared__ int part[1024];
    int t = threadIdx.x;
    int base = t * 8;
    int loc[8];
    int s = 0;
#pragma unroll
    for (int i = 0; i < 8; i++) { loc[i] = s; s += g_cnt[base + i]; }
    part[t] = s;
    __syncthreads();
    int val = s;
    for (int off = 1; off < 1024; off <<= 1) {
        int v = (t >= off) ? part[t - off] : 0;
        __syncthreads();
        val += v;
        part[t] = val;
        __syncthreads();
    }
    int pre = (t == 0) ? 0 : part[t - 1];
#pragma unroll
    for (int i = 0; i < 8; i++) g_offm[base + i] = pre + loc[i];
}

__global__ void k_place(const int* __restrict__ ei) {
    int e = blockIdx.x * blockDim.x + threadIdx.x;
    if (e < EE) {
        int c = ei[EE + e];
        int p = atomicAdd(&g_offm[c], 1);
        g_perm[p] = e;
    }
}

__global__ void k_build(const int* __restrict__ ei, const float* __restrict__ ew,
                        const float* __restrict__ means, const float* __restrict__ betas) {
    int warp = (blockIdx.x * blockDim.x + threadIdx.x) >> 5;
    int lane = threadIdx.x & 31;
    if (warp >= EE) return;
    int e = g_perm[warp];
    int r = ei[e];
    int c = ei[EE + e];
    float d = ew[e];
    float cut = 0.5f * (cosf(d * 0.628318530717958647692f) + 1.0f);
    if (!(d < 5.0f)) cut = 0.f;
    float ex = __expf(-d);
    size_t ro = (size_t)warp * K1;
    {
        float m = means[lane], b = betas[lane];
        float v = ex - m;
        g_rbf[ro + lane] = __float2half_rn(cut * __expf(-b * v * v));
    }
    int k2 = lane + 32;
    float val2 = 0.f;
    if (k2 < NRBF) {
        float m = means[k2], b = betas[k2];
        float v = ex - m;
        val2 = cut * __expf(-b * v * v);
    }
    g_rbf[ro + k2] = __float2half_rn(val2);
    if (lane == 0) {
        g_cut[warp]  = cut;
        g_cutm[warp] = (r != c) ? cut : 0.f;
        g_srow[warp] = r;
        g_sdst[warp] = c;
    }
}

__global__ void k_gather(const int* __restrict__ z, const float* __restrict__ emb,
                         const float* __restrict__ neemb) {
    int i = blockIdx.x * blockDim.x + threadIdx.x;
    if (i >= NN * HID) return;
    int n = i >> 7, c = i & 127;
    int zi = z[n];
    g_x[i]   = emb[zi * HID + c];
    g_nex[i] = neemb[zi * HID + c];
    g_agg[i] = 0.f;
}

// weight prep
__global__ void k_wprep1(const float* __restrict__ w, int mode, int layers) {
    int i = blockIdx.x * blockDim.x + threadIdx.x;
    if (i >= layers * HID * K1) return;
    int k = i & (K1 - 1);
    int n = (i >> 6) & (HID - 1);
    int l = i >> 13;
    float v = (k < NRBF) ? w[((size_t)l * NRBF + k) * HID + n] : 0.f;
    h16 hi = __float2half_rn(v);
    h16 lo = __float2half_rn(v - __half2float(hi));
    if (mode == 0) { g_w1t_hi[i] = hi; g_w1t_lo[i] = lo; }
    else           { g_npt_hi[i] = hi; g_npt_lo[i] = lo; }
}

__global__ void k_wprep2(const float* __restrict__ w) {
    int i = blockIdx.x * blockDim.x + threadIdx.x;
    if (i >= NLAY * HID * HID) return;
    int k = i & (HID - 1);
    int n = (i >> 7) & (HID - 1);
    int l = i >> 14;
    float v = w[((size_t)l * HID + k) * HID + n];
    h16 hi = __float2half_rn(v);
    g_w2t_hi[i] = hi;
    g_w2t_lo[i] = __float2half_rn(v - __half2float(hi));
}

__global__ void k_wprepAll(const float* __restrict__ necatw, const float* __restrict__ lin1w,
                           const float* __restrict__ lin2w, const float* __restrict__ linw) {
    int slot = blockIdx.x >> 6;
    int i = (blockIdx.x & 63) * 256 + threadIdx.x;
    const float* src;
    if (slot < 2)       src = necatw + (size_t)slot * HID * HID;
    else if (slot < 8)  src = lin1w + (size_t)(slot - 2) * HID * HID;
    else if (slot < 14) src = lin2w + (size_t)(slot - 8) * HID * HID;
    else                src = linw  + (size_t)(slot - 14) * HID * HID;
    int k = i & (HID - 1);
    int n = i >> 7;
    float v = src[k * HID + n];
    h16 hi = __float2half_rn(v);
    g_nwt_hi[(size_t)slot * HID * HID + i] = hi;
    g_nwt_lo[(size_t)slot * HID * HID + i] = __float2half_rn(v - __half2float(hi));
}

// ---------------- warp-MMA helpers (fp16) ----------------
__device__ __forceinline__ void mma16816(float c[4], const unsigned a[4], const unsigned b[2]) {
    asm volatile(
        "mma.sync.aligned.m16n8k16.row.col.f32.f16.f16.f32 "
        "{%0,%1,%2,%3}, {%4,%5,%6,%7}, {%8,%9}, {%0,%1,%2,%3};\n"
        : "+f"(c[0]), "+f"(c[1]), "+f"(c[2]), "+f"(c[3])
        : "r"(a[0]), "r"(a[1]), "r"(a[2]), "r"(a[3]), "r"(b[0]), "r"(b[1]));
}

__device__ __forceinline__ void ldsm4(unsigned r[4], unsigned addr) {
    asm volatile("ldmatrix.sync.aligned.m8n8.x4.shared.b16 {%0,%1,%2,%3}, [%4];"
        : "=r"(r[0]), "=r"(r[1]), "=r"(r[2]), "=r"(r[3]) : "r"(addr));
}

__device__ __forceinline__ unsigned a_addr(unsigned base, int m0, int PB, int lane) {
    int sel = lane >> 3, li = lane & 7;
    return base + (m0 + li + (sel & 1) * 8) * PB + ((sel >> 1) * 8) * 2;
}
__device__ __forceinline__ unsigned b_addr(unsigned base, int n0, int PB, int lane) {
    int sel = lane >> 3, li = lane & 7;
    return base + (n0 + li + (sel >> 1) * 8) * PB + ((sel & 1) * 8) * 2;
}

// 32x64 warp GEMM: acc += A*(Bhi+Blo); A single fp16, B split
template <int KSTEPS, int PB>
__device__ __forceinline__ void wgemm64(unsigned aA, unsigned bHi, unsigned bLo,
                                        float acc[2][8][4]) {
#pragma unroll
    for (int ks = 0; ks < KSTEPS; ks++) {
        unsigned off = ks * 32;
        unsigned a0[4], a1[4];
        ldsm4(a0, aA + off);
        ldsm4(a1, aA + 16 * PB + off);
#pragma unroll
        for (int half = 0; half < 2; half++) {
            unsigned hb = half * 32 * PB;
            unsigned bh0[4], bh1[4], bl0[4], bl1[4];
            ldsm4(bh0, bHi + hb + off);
            ldsm4(bh1, bHi + hb + 16 * PB + off);
            ldsm4(bl0, bLo + hb + off);
            ldsm4(bl1, bLo + hb + 16 * PB + off);
#pragma unroll
            for (int q = 0; q < 4; q++) {
                int nt = half * 4 + q;
                const unsigned* bh = (q < 2) ? (bh0 + 2 * q) : (bh1 + 2 * (q - 2));
                const unsigned* bl = (q < 2) ? (bl0 + 2 * q) : (bl1 + 2 * (q - 2));
                mma16816(acc[0][nt], a0, bh);
                mma16816(acc[1][nt], a1, bh);
                mma16816(acc[0][nt], a0, bl);
                mma16816(acc[1][nt], a1, bl);
            }
        }
    }
}

// 32x32 warp GEMM (node kernels)
template <int KSTEPS, int PB>
__device__ __forceinline__ void wgemm2(unsigned aA, unsigned bHi, unsigned bLo,
                                       float acc[2][4][4]) {
#pragma unroll
    for (int ks = 0; ks < KSTEPS; ks++) {
        unsigned off = ks * 32;
        unsigned a0[4], a1[4], bh0[4], bh1[4], bl0[4], bl1[4];
        ldsm4(a0, aA + off);
        ldsm4(a1, aA + 16 * PB + off);
        ldsm4(bh0, bHi + off);
        ldsm4(bh1, bHi + 16 * PB + off);
        ldsm4(bl0, bLo + off);
        ldsm4(bl1, bLo + 16 * PB + off);
#pragma unroll
        for (int nt = 0; nt < 4; nt++) {
            const unsigned* bh = (nt < 2) ? (bh0 + 2 * nt) : (bh1 + 2 * (nt - 2));
            const unsigned* bl = (nt < 2) ? (bl0 + 2 * nt) : (bl1 + 2 * (nt - 2));
            mma16816(acc[0][nt], a0, bh);
            mma16816(acc[1][nt], a1, bh);
            mma16816(acc[0][nt], a0, bl);
            mma16816(acc[1][nt], a1, bl);
        }
    }
}

// ---------------- cp.async helpers ----------------
__device__ __forceinline__ void cpa16(unsigned saddr, const void* gaddr) {
    asm volatile("cp.async.ca.shared.global [%0], [%1], 16;" :: "r"(saddr), "l"(gaddr));
}
__device__ __forceinline__ void cpa_commit() { asm volatile("cp.async.commit_group;"); }
__device__ __forceinline__ void cpa_wait0()  { asm volatile("cp.async.wait_group 0;"); }
#define BAR1() asm volatile("bar.sync 1, 256;" ::: "memory")

// ---------------- warp-specialized edge kernel ----------------
// warps 0-7: GEMM pipeline for tile t ; warps 8-15: aggregation of tile t-1.
// smem (interaction): W1hi[0) W1lo[18432) W2hi[36864) W2lo[71680)
//   rbf[106496,+18432) FB0[124928,+34816) FB1[159744,+34816) misc[194560,+4608)
// NE: W1hi[0) W1lo[18432) rbf[36864,+18432) FB0[55296) FB1[90112) misc[124928)
template <int NE>
__global__ void __launch_bounds__(512, 1)
k_edge(int layer, const float* __restrict__ b1g, const float* __restrict__ b2g) {
    extern __shared__ __align__(16) char smref[];
    constexpr int R_BYTES  = HID * PR * 2;   // 18432
    constexpr int W2_BYTES = HID * PT * 2;   // 34816
    constexpr int FB_BYTES = HID * PT * 2;   // 34816 (fp16, pitch PT)
    const int OFF_W1HI = 0;
    const int OFF_W1LO = R_BYTES;
    const int OFF_W2HI = 2 * R_BYTES;                 // interaction only
    const int OFF_W2LO = OFF_W2HI + W2_BYTES;
    const int OFF_R    = NE ? (2 * R_BYTES) : (OFF_W2LO + W2_BYTES);
    const int OFF_FB   = OFF_R + R_BYTES;             // two buffers of FB_BYTES
    const int OFF_MISC = OFF_FB + 2 * FB_BYTES;
    const int OFF_CUT  = OFF_MISC;          // [3][128] f32
    const int OFF_ROW  = OFF_MISC + 1536;   // [3][128] i32
    const int OFF_DST  = OFF_MISC + 3072;   // [3][128] i32
    const int OFF_B1   = OFF_MISC + 4608;
    const int OFF_B2   = OFF_MISC + 5120;

    float* sB1 = (float*)(smref + OFF_B1);
    float* sB2 = (float*)(smref + OFF_B2);

    int tid = threadIdx.x;
    unsigned sbase = (unsigned)__cvta_generic_to_shared(smref);
    const long NT = EE / 128;

    // ---- stage weights once (all threads) ----
    {
        const unsigned* ghi = (const unsigned*)(NE ? g_npt_hi : (g_w1t_hi + (size_t)layer * HID * K1));
        const unsigned* glo = (const unsigned*)(NE ? g_npt_lo : (g_w1t_lo + (size_t)layer * HID * K1));
        unsigned* shi = (unsigned*)(smref + OFF_W1HI);
        unsigned* slo = (unsigned*)(smref + OFF_W1LO);
        for (int i = tid; i < 128 * 32; i += 512) {
            int r = i >> 5, wd = i & 31;
            shi[r * (PR / 2) + wd] = ghi[i];
            slo[r * (PR / 2) + wd] = glo[i];
        }
    }
    if (!NE) {
        const unsigned* ghi = (const unsigned*)(g_w2t_hi + (size_t)layer * HID * HID);
        const unsigned* glo = (const unsigned*)(g_w2t_lo + (size_t)layer * HID * HID);
        unsigned* shi = (unsigned*)(smref + OFF_W2HI);
        unsigned* slo = (unsigned*)(smref + OFF_W2LO);
        for (int i = tid; i < 128 * 64; i += 512) {
            int r = i >> 6, wd = i & 63;
            shi[r * (PT / 2) + wd] = ghi[i];
            slo[r * (PT / 2) + wd] = glo[i];
        }
    }
    if (tid < 128) {
        sB1[tid] = b1g[tid];
        sB2[tid] = NE ? 0.f : b2g[tid];
    }

    // ---- priming prefetch: tile blockIdx.x -> rbf + meta slot 0 (GEMM threads)
    if (tid < 256) {
        long ebase = (long)blockIdx.x * 128;
        for (int c = tid; c < 1024; c += 256) {
            int r = c >> 3, ch = c & 7;
            cpa16(sbase + OFF_R + r * (PR * 2) + ch * 16, &g_rbf[(ebase + r) * K1 + ch * 8]);
        }
        if (tid < 32) {
            const float* cs = NE ? g_cutm : g_cut;
            cpa16(sbase + OFF_CUT + tid * 16, cs + ebase + tid * 4);
        } else if (tid < 64) {
            int t = tid - 32;
            cpa16(sbase + OFF_ROW + t * 16, g_srow + ebase + t * 4);
        } else if (tid < 96) {
            int t = tid - 64;
            cpa16(sbase + OFF_DST + t * 16, g_sdst + ebase + t * 4);
        }
        cpa_commit();
    }

    // GEMM warp tiling: 8 warps, 32x64 tiles (4m x 2n)
    int w = tid >> 5, lane = tid & 31;
    int m0 = (w & 3) * 32, n0 = (w >> 2) * 64;
    int g = lane >> 2, tc = lane & 3;
    unsigned g1a   = a_addr(sbase + OFF_R,    m0, PR * 2, lane);
    unsigned g1bHi = b_addr(sbase + OFF_W1HI, n0, PR * 2, lane);
    unsigned g1bLo = g1bHi + R_BYTES;
    unsigned g2bHi = b_addr(sbase + OFF_W2HI, n0, PT * 2, lane);
    unsigned g2bLo = g2bHi + W2_BYTES;

    const float* hsrc = NE ? g_nex : g_h;

    int it = 0;
    for (long tg = blockIdx.x; ; tg += gridDim.x, it++) {
        bool has_g = (tg < NT);
        bool has_a = (it >= 1) && (tg - gridDim.x < NT);
        if (!has_g && !has_a) break;
        __syncthreads();   // hand off F[it-1] to agg; F[it] buffer free

        if (tid < 256) {
            if (has_g) {
                int slot = it % 3;
                int fb = it & 1;
                float* sCut = (float*)(smref + OFF_CUT + slot * 512);
                h16* sFB = (h16*)(smref + OFF_FB + fb * FB_BYTES);

                cpa_wait0();
                BAR1();   // rbf + meta visible to all GEMM warps

                // ---- GEMM1: rbf[128,64] @ W1[64,128] ----
                float acc[2][8][4];
#pragma unroll
                for (int a = 0; a < 2; a++)
#pragma unroll
                    for (int b = 0; b < 8; b++)
#pragma unroll
                        for (int c = 0; c < 4; c++) acc[a][b][c] = 0.f;
                wgemm64<K1 / 16, PR * 2>(g1a, g1bHi, g1bLo, acc);

                if (NE) {
                    // F = (acc + b1) * cutm  -> fp16 FB
#pragma unroll
                    for (int mt = 0; mt < 2; mt++) {
                        int ra = m0 + mt * 16 + g, rb2 = ra + 8;
                        float cua = sCut[ra], cub = sCut[rb2];
#pragma unroll
                        for (int nt = 0; nt < 8; nt++) {
                            int col = n0 + nt * 8 + 2 * tc;
                            *(h162*)&sFB[ra * PT + col] = __floats2half2_rn(
                                (acc[mt][nt][0] + sB1[col]) * cua,
                                (acc[mt][nt][1] + sB1[col + 1]) * cua);
                            *(h162*)&sFB[rb2 * PT + col] = __floats2half2_rn(
                                (acc[mt][nt][2] + sB1[col]) * cub,
                                (acc[mt][nt][3] + sB1[col + 1]) * cub);
                        }
                    }
                } else {
                    // T = silu(acc + b1) -> fp16 FB (as GEMM2 A operand)
#pragma unroll
                    for (int mt = 0; mt < 2; mt++) {
                        int ra = m0 + mt * 16 + g, rb2 = ra + 8;
#pragma unroll
                        for (int nt = 0; nt < 8; nt++) {
                            int col = n0 + nt * 8 + 2 * tc;
                            float x0 = acc[mt][nt][0] + sB1[col];
                            float x1 = acc[mt][nt][1] + sB1[col + 1];
                            float x2 = acc[mt][nt][2] + sB1[col];
                            float x3 = acc[mt][nt][3] + sB1[col + 1];
                            x0 = x0 / (1.f + __expf(-x0));
                            x1 = x1 / (1.f + __expf(-x1));
                            x2 = x2 / (1.f + __expf(-x2));
                            x3 = x3 / (1.f + __expf(-x3));
                            *(h162*)&sFB[ra * PT + col]  = __floats2half2_rn(x0, x1);
                            *(h162*)&sFB[rb2 * PT + col] = __floats2half2_rn(x2, x3);
                        }
                    }
                }
                BAR1();   // rbf reads done; T (or F) visible

                // ---- prefetch next tile ----
                {
                    long nxt = tg + gridDim.x;
                    if (nxt < NT) {
                        long ebase = nxt * 128;
                        int ns = (it + 1) % 3;
                        for (int c = tid; c < 1024; c += 256) {
                            int r = c >> 3, ch = c & 7;
                            cpa16(sbase + OFF_R + r * (PR * 2) + ch * 16,
                                  &g_rbf[(ebase + r) * K1 + ch * 8]);
                        }
                        if (tid < 32) {
                            const float* cs = NE ? g_cutm : g_cut;
                            cpa16(sbase + OFF_CUT + ns * 512 + tid * 16, cs + ebase + tid * 4);
                        } else if (tid < 64) {
                            int t = tid - 32;
                            cpa16(sbase + OFF_ROW + ns * 512 + t * 16, g_srow + ebase + t * 4);
                        } else if (tid < 96) {
                            int t = tid - 64;
                            cpa16(sbase + OFF_DST + ns * 512 + t * 16, g_sdst + ebase + t * 4);
                        }
                    }
                    cpa_commit();
                }

                if (!NE) {
                    // ---- GEMM2: T[128,128] @ W2[128,128] ----
                    unsigned g2a = a_addr(sbase + OFF_FB + fb * FB_BYTES, m0, PT * 2, lane);
#pragma unroll
                    for (int a = 0; a < 2; a++)
#pragma unroll
                        for (int b = 0; b < 8; b++)
#pragma unroll
                            for (int c = 0; c < 4; c++) acc[a][b][c] = 0.f;
                    wgemm64<HID / 16, PT * 2>(g2a, g2bHi, g2bLo, acc);
                    BAR1();   // all T reads done before F overwrite

                    // F = (acc + b2) * cut -> fp16 FB (overwrite T)
#pragma unroll
                    for (int mt = 0; mt < 2; mt++) {
                        int ra = m0 + mt * 16 + g, rb2 = ra + 8;
                        float cua = sCut[ra], cub = sCut[rb2];
#pragma unroll
                        for (int nt = 0; nt < 8; nt++) {
                            int col = n0 + nt * 8 + 2 * tc;
                            *(h162*)&sFB[ra * PT + col] = __floats2half2_rn(
                                (acc[mt][nt][0] + sB2[col]) * cua,
                                (acc[mt][nt][1] + sB2[col + 1]) * cua);
                            *(h162*)&sFB[rb2 * PT + col] = __floats2half2_rn(
                                (acc[mt][nt][2] + sB2[col]) * cub,
                                (acc[mt][nt][3] + sB2[col + 1]) * cub);
                        }
                    }
                }
            }
        } else {
            if (has_a) {
                int pslot = (it + 2) % 3;        // (it-1) mod 3
                int pfb = (it & 1) ^ 1;          // (it-1) & 1
                const h16* sFB = (const h16*)(smref + OFF_FB + pfb * FB_BYTES);
                int* sRow = (int*)(smref + OFF_ROW + pslot * 512);
                int* sDst = (int*)(smref + OFF_DST + pslot * 512);

                int tid2 = tid - 256;
                int grp = tid2 >> 7;
                int f = tid2 & 127;
                int e0 = grp * 64;
                float accv = 0.f;
                int cur = sDst[e0];
#pragma unroll 1
                for (int b = 0; b < 8; b++) {
                    float hb[8];
#pragma unroll
                    for (int j = 0; j < 8; j++)
                        hb[j] = hsrc[(long)sRow[e0 + b * 8 + j] * HID + f];
#pragma unroll
                    for (int j = 0; j < 8; j++) {
                        int e = e0 + b * 8 + j;
                        int dd = sDst[e];
                        if (dd != cur) {
                            atomicAdd(&g_agg[(long)cur * HID + f], accv);
                            accv = 0.f;
                            cur = dd;
                        }
                        accv = fmaf(hb[j], __half2float(sFB[e * PT + f]), accv);
                    }
                }
                atomicAdd(&g_agg[(long)cur * HID + f], accv);
            }
        }
    }
}

// ---------------- node-kernel shared pieces (unchanged from R9) --------------
#define NA_BYTES  (64 * PT * 2)
#define NW_BYTES  (HID * PT * 2)
#define NOFF_A    0
#define NOFF_WA   NA_BYTES
#define NOFF_WB   (NOFF_WA + 2 * NW_BYTES)
#define NOFF_H    (NOFF_WB + 2 * NW_BYTES)
#define NOFF_B    (NOFF_H + NA_BYTES)
#define NSM_TOTAL (NOFF_B + 1024)

__device__ __forceinline__ void stageA_f16(char* smref, int off, const float* src,
                                           int rb, int tid) {
    h16* dst = (h16*)(smref + off);
    for (int i = tid; i < 64 * HID; i += 256) {
        int r = i >> 7, k = i & 127;
        dst[r * PT + k] = __float2half_rn(src[(long)(rb + r) * HID + k]);
    }
}

__device__ __forceinline__ void stageW(char* smref, int off, int slot, int tid) {
    const unsigned* ghi = (const unsigned*)(g_nwt_hi + (size_t)slot * HID * HID);
    const unsigned* glo = (const unsigned*)(g_nwt_lo + (size_t)slot * HID * HID);
    unsigned* shi = (unsigned*)(smref + off);
    unsigned* slo = (unsigned*)(smref + off + NW_BYTES);
    for (int i = tid; i < 128 * 64; i += 256) {
        int r = i >> 6, wd = i & 63;
        shi[r * (PT / 2) + wd] = ghi[i];
        slo[r * (PT / 2) + wd] = glo[i];
    }
}

__global__ void __launch_bounds__(256, 1)
k_nodeNE(const float* __restrict__ necatb) {
    extern __shared__ __align__(16) char smref[];
    float* sBa = (float*)(smref + NOFF_B);

    int tid = threadIdx.x;
    int rb = blockIdx.x * 64;
    unsigned sbase = (unsigned)__cvta_generic_to_shared(smref);

    stageA_f16(smref, NOFF_A, g_x, rb, tid);
    stageW(smref, NOFF_WA, 0, tid);
    stageW(smref, NOFF_WB, 1, tid);
    if (tid < 128) sBa[tid] = necatb[tid];
    __syncthreads();

    int w = tid >> 5, lane = tid & 31;
    int m0 = (w & 1) * 32, n0 = (w >> 1) * 32;
    int g = lane >> 2, tc = lane & 3;

    float acc[2][4][4];
#pragma unroll
    for (int a = 0; a < 2; a++)
#pragma unroll
        for (int b = 0; b < 4; b++)
#pragma unroll
            for (int c = 0; c < 4; c++) acc[a][b][c] = 0.f;

    {
        unsigned aA = a_addr(sbase + NOFF_A, m0, PT * 2, lane);
        unsigned bHi = b_addr(sbase + NOFF_WA, n0, PT * 2, lane);
        wgemm2<HID / 16, PT * 2>(aA, bHi, bHi + NW_BYTES, acc);
    }
    __syncthreads();

    stageA_f16(smref, NOFF_A, g_agg, rb, tid);
    stageW(smref, NOFF_WA, 2, tid);
    __syncthreads();

    {
        float4* za = (float4*)(g_agg + (long)rb * HID);
        for (int i = tid; i < 64 * HID / 4; i += 256) za[i] = make_float4(0.f, 0.f, 0.f, 0.f);
    }

    {
        unsigned aA = a_addr(sbase + NOFF_A, m0, PT * 2, lane);
        unsigned bHi = b_addr(sbase + NOFF_WB, n0, PT * 2, lane);
        wgemm2<HID / 16, PT * 2>(aA, bHi, bHi + NW_BYTES, acc);

        h16* xh = (h16*)(smref + NOFF_H);
#pragma unroll
        for (int mt = 0; mt < 2; mt++) {
#pragma unroll
            for (int dr = 0; dr < 2; dr++) {
                int r = m0 + mt * 16 + g + dr * 8;
                long ro = (long)(rb + r) * HID;
#pragma unroll
                for (int nt = 0; nt < 4; nt++) {
                    int col = n0 + nt * 8 + 2 * tc;
                    float v0 = acc[mt][nt][2 * dr]     + sBa[col];
                    float v1 = acc[mt][nt][2 * dr + 1] + sBa[col + 1];
                    *(float2*)&g_x[ro + col] = make_float2(v0, v1);
                    *(h162*)&xh[r * PT + col] = __floats2half2_rn(v0, v1);
                }
            }
        }
    }
    __syncthreads();

    {
        float acc2[2][4][4];
#pragma unroll
        for (int a = 0; a < 2; a++)
#pragma unroll
            for (int b = 0; b < 4; b++)
#pragma unroll
                for (int c = 0; c < 4; c++) acc2[a][b][c] = 0.f;
        unsigned aA = a_addr(sbase + NOFF_H, m0, PT * 2, lane);
        unsigned bHi = b_addr(sbase + NOFF_WA, n0, PT * 2, lane);
        wgemm2<HID / 16, PT * 2>(aA, bHi, bHi + NW_BYTES, acc2);
#pragma unroll
        for (int mt = 0; mt < 2; mt++) {
#pragma unroll
            for (int dr = 0; dr < 2; dr++) {
                int r = m0 + mt * 16 + g + dr * 8;
                long ro = (long)(rb + r) * HID;
#pragma unroll
                for (int nt = 0; nt < 4; nt++) {
                    int col = n0 + nt * 8 + 2 * tc;
                    *(float2*)&g_h[ro + col] =
                        make_float2(acc2[mt][nt][2 * dr], acc2[mt][nt][2 * dr + 1]);
                }
            }
        }
    }
}

__global__ void __launch_bounds__(256, 1)
k_nodeL(int l, int last, const float* __restrict__ b2g, const float* __restrict__ b3g,
        float* dout) {
    extern __shared__ __align__(16) char smref[];
    float* sB2 = (float*)(smref + NOFF_B);
    float* sB3 = sB2 + 128;

    int tid = threadIdx.x;
    int rb = blockIdx.x * 64;
    unsigned sbase = (unsigned)__cvta_generic_to_shared(smref);

    stageA_f16(smref, NOFF_A, g_agg, rb, tid);
    stageW(smref, NOFF_WA, 8 + l, tid);
    stageW(smref, NOFF_WB, 14 + l, tid);
    if (tid < 128) { sB2[tid] = b2g[tid]; sB3[tid] = b3g[tid]; }
    __syncthreads();

    int w = tid >> 5, lane = tid & 31;
    int m0 = (w & 1) * 32, n0 = (w >> 1) * 32;
    int g = lane >> 2, tc = lane & 3;

    {
        float acc[2][4][4];
#pragma unroll
        for (int a = 0; a < 2; a++)
#pragma unroll
            for (int b = 0; b < 4; b++)
#pragma unroll
                for (int c = 0; c < 4; c++) acc[a][b][c] = 0.f;
        unsigned aA = a_addr(sbase + NOFF_A, m0, PT * 2, lane);
        unsigned bHi = b_addr(sbase + NOFF_WA, n0, PT * 2, lane);
        wgemm2<HID / 16, PT * 2>(aA, bHi, bHi + NW_BYTES, acc);

        h16* sH = (h16*)(smref + NOFF_H);
#pragma unroll
        for (int mt = 0; mt < 2; mt++) {
            int ra = m0 + mt * 16 + g, rb2 = ra + 8;
#pragma unroll
            for (int nt = 0; nt < 4; nt++) {
                int col = n0 + nt * 8 + 2 * tc;
                float x0 = acc[mt][nt][0] + sB2[col];
                float x1 = acc[mt][nt][1] + sB2[col + 1];
                float x2 = acc[mt][nt][2] + sB2[col];
                float x3 = acc[mt][nt][3] + sB2[col + 1];
                x0 = x0 / (1.f + __expf(-x0));
                x1 = x1 / (1.f + __expf(-x1));
                x2 = x2 / (1.f + __expf(-x2));
                x3 = x3 / (1.f + __expf(-x3));
                *(h162*)&sH[ra * PT + col]  = __floats2half2_rn(x0, x1);
                *(h162*)&sH[rb2 * PT + col] = __floats2half2_rn(x2, x3);
            }
        }
    }
    __syncthreads();

    if (!last) {
        stageW(smref, NOFF_WA, 2 + (l + 1), tid);
        float4* za = (float4*)(g_agg + (long)rb * HID);
        for (int i = tid; i < 64 * HID / 4; i += 256) za[i] = make_float4(0.f, 0.f, 0.f, 0.f);
    }

    {
        float acc[2][4][4];
#pragma unroll
        for (int a = 0; a < 2; a++)
#pragma unroll
            for (int b = 0; b < 4; b++)
#pragma unroll
                for (int c = 0; c < 4; c++) acc[a][b][c] = 0.f;
        unsigned aA = a_addr(sbase + NOFF_H, m0, PT * 2, lane);
        unsigned bHi = b_addr(sbase + NOFF_WB, n0, PT * 2, lane);
        wgemm2<HID / 16, PT * 2>(aA, bHi, bHi + NW_BYTES, acc);

        float* out = last ? dout : g_x;
        h16* xh = (h16*)(smref + NOFF_A);
#pragma unroll
        for (int mt = 0; mt < 2; mt++) {
#pragma unroll
            for (int dr = 0; dr < 2; dr++) {
                int r = m0 + mt * 16 + g + dr * 8;
                long ro = (long)(rb + r) * HID;
#pragma unroll
                for (int nt = 0; nt < 4; nt++) {
                    int col = n0 + nt * 8 + 2 * tc;
                    float v0 = acc[mt][nt][2 * dr]     + sB3[col] + g_x[ro + col];
                    float v1 = acc[mt][nt][2 * dr + 1] + sB3[col + 1] + g_x[ro + col + 1];
                    *(float2*)&out[ro + col] = make_float2(v0, v1);
                    if (!last)
                        *(h162*)&xh[r * PT + col] = __floats2half2_rn(v0, v1);
                }
            }
        }
    }
    if (last) return;
    __syncthreads();

    {
        float acc[2][4][4];
#pragma unroll
        for (int a = 0; a < 2; a++)
#pragma unroll
            for (int b = 0; b < 4; b++)
#pragma unroll
                for (int c = 0; c < 4; c++) acc[a][b][c] = 0.f;
        unsigned aA = a_addr(sbase + NOFF_A, m0, PT * 2, lane);
        unsigned bHi = b_addr(sbase + NOFF_WA, n0, PT * 2, lane);
        wgemm2<HID / 16, PT * 2>(aA, bHi, bHi + NW_BYTES, acc);
#pragma unroll
        for (int mt = 0; mt < 2; mt++) {
#pragma unroll
            for (int dr = 0; dr < 2; dr++) {
                int r = m0 + mt * 16 + g + dr * 8;
                long ro = (long)(rb + r) * HID;
#pragma unroll
                for (int nt = 0; nt < 4; nt++) {
                    int col = n0 + nt * 8 + 2 * tc;
                    *(float2*)&g_h[ro + col] =
                        make_float2(acc[mt][nt][2 * dr], acc[mt][nt][2 * dr + 1]);
                }
            }
        }
    }
}

// ---------------- launch ----------------
extern "C" void kernel_launch(void* const* d_in, const int* in_sizes, int n_in,
                              void* d_out, int out_size) {
    const int*   z       = (const int*)d_in[0];
    const int*   ei      = (const int*)d_in[1];
    const float* ew      = (const float*)d_in[2];
    const float* emb     = (const float*)d_in[3];
    const float* neemb   = (const float*)d_in[4];
    const float* neprojw = (const float*)d_in[5];
    const float* neprojb = (const float*)d_in[6];
    const float* necatw  = (const float*)d_in[7];
    const float* necatb  = (const float*)d_in[8];
    const float* means   = (const float*)d_in[9];
    const float* betas   = (const float*)d_in[10];
    const float* mlpw1   = (const float*)d_in[11];
    const float* mlpb1   = (const float*)d_in[12];
    const float* mlpw2   = (const float*)d_in[13];
    const float* mlpb2   = (const float*)d_in[14];
    const float* lin1w   = (const float*)d_in[15];
    const float* lin2w   = (const float*)d_in[16];
    const float* lin2b   = (const float*)d_in[17];
    const float* linw    = (const float*)d_in[18];
    const float* linb    = (const float*)d_in[19];
    float* outp = (float*)d_out;

    const int R_BYTES = HID * PR * 2, W2B = HID * PT * 2, FBB = HID * PT * 2;
    const int smI = 2 * R_BYTES + 2 * W2B + R_BYTES + 2 * FBB + 5632;   // 199168... compute: 36864+69632+18432+69632+5632 = 200192
    const int smN = 2 * R_BYTES + R_BYTES + 2 * FBB + 5632;             // 130560

    cudaFuncSetAttribute(k_edge<0>, cudaFuncAttributeMaxDynamicSharedMemorySize, smI);
    cudaFuncSetAttribute(k_edge<1>, cudaFuncAttributeMaxDynamicSharedMemorySize, smN);
    cudaFuncSetAttribute(k_nodeNE,  cudaFuncAttributeMaxDynamicSharedMemorySize, NSM_TOTAL);
    cudaFuncSetAttribute(k_nodeL,   cudaFuncAttributeMaxDynamicSharedMemorySize, NSM_TOTAL);

    // ---- sort edges by destination + precompute per-edge data ----
    k_zero_cnt<<<NN / 256, 256>>>();
    k_hist<<<EE / 256, 256>>>(ei);
    k_scan<<<1, 1024>>>();
    k_place<<<EE / 256, 256>>>(ei);
    k_build<<<EE / 8, 256>>>(ei, ew, means, betas);
    k_gather<<<NN * HID / 256, 256>>>(z, emb, neemb);

    // ---- weight prep ----
    k_wprep1<<<(NLAY * HID * K1 + 255) / 256, 256>>>(mlpw1, 0, NLAY);
    k_wprep1<<<(HID * K1 + 255) / 256, 256>>>(neprojw, 1, 1);
    k_wprep2<<<(NLAY * HID * HID + 255) / 256, 256>>>(mlpw2);
    k_wprepAll<<<NSLOT * 64, 256>>>(necatw, lin1w, lin2w, linw);

    // ---- NeighborEmbedding + initial lin1 ----
    k_edge<1><<<148, 512, smN>>>(0, neprojb, nullptr);
    k_nodeNE<<<NN / 64, 256, NSM_TOTAL>>>(necatb);

    // ---- interaction layers ----
    for (int l = 0; l < NLAY; l++) {
        k_edge<0><<<148, 512, smI>>>(l, mlpb1 + (size_t)l * HID, mlpb2 + (size_t)l * HID);
        k_nodeL<<<NN / 64, 256, NSM_TOTAL>>>(l, l == NLAY - 1,
                                             lin2b + (size_t)l * HID,
                                             linb + (size_t)l * HID, outp);
    }
}

// round 12
// speedup vs baseline: 1.0913x; 1.0913x over previous
#include <cuda_runtime.h>
#include <cuda_fp16.h>
#include <math.h>

// ---------------- problem constants ----------------
#define NN    8192
#define EE    262144
#define HID   128
#define NRBF  50
#define K1    64
#define NLAY  6
#define PR    72           // smem pitch (fp16) for rbf / W1^T
#define PT    136          // smem pitch (fp16) for T / W2^T / F / node tiles
#define PH    132          // smem pitch (f32) for gathered-h stage
#define NSLOT 20

typedef __half  h16;
typedef __half2 h162;

// ---------------- device scratch ----------------
__device__ __align__(16) h16 g_rbf[(size_t)EE * K1];
__device__ __align__(16) h16 g_w1t_hi[NLAY * HID * K1];
__device__ __align__(16) h16 g_w1t_lo[NLAY * HID * K1];
__device__ __align__(16) h16 g_w2t_hi[NLAY * HID * HID];
__device__ __align__(16) h16 g_w2t_lo[NLAY * HID * HID];
__device__ __align__(16) h16 g_npt_hi[HID * K1];
__device__ __align__(16) h16 g_npt_lo[HID * K1];
__device__ __align__(16) h16 g_nwt_hi[NSLOT * HID * HID];
__device__ __align__(16) h16 g_nwt_lo[NSLOT * HID * HID];
__device__ float g_cut[EE];
__device__ float g_cutm[EE];
__device__ int   g_srow[EE];
__device__ int   g_sdst[EE];
__device__ int   g_perm[EE];
__device__ int   g_cnt[NN];
__device__ int   g_offm[NN];
__device__ float g_x  [NN * HID];
__device__ float g_h  [NN * HID];
__device__ float g_agg[NN * HID];
__device__ float g_nex[NN * HID];

// ---------------- small helper kernels ----------------
__global__ void k_zero_cnt() {
    int i = blockIdx.x * blockDim.x + threadIdx.x;
    if (i < NN) g_cnt[i] = 0;
}

__global__ void k_hist(const int* __restrict__ ei) {
    int e = blockIdx.x * blockDim.x + threadIdx.x;
    if (e < EE) atomicAdd(&g_cnt[ei[EE + e]], 1);
}

__global__ void k_scan() {
    __shared__ int part[1024];
    int t = threadIdx.x;
    int base = t * 8;
    int loc[8];
    int s = 0;
#pragma unroll
    for (int i = 0; i < 8; i++) { loc[i] = s; s += g_cnt[base + i]; }
    part[t] = s;
    __syncthreads();
    int val = s;
    for (int off = 1; off < 1024; off <<= 1) {
        int v = (t >= off) ? part[t - off] : 0;
        __syncthreads();
        val += v;
        part[t] = val;
        __syncthreads();
    }
    int pre = (t == 0) ? 0 : part[t - 1];
#pragma unroll
    for (int i = 0; i < 8; i++) g_offm[base + i] = pre + loc[i];
}

__global__ void k_place(const int* __restrict__ ei) {
    int e = blockIdx.x * blockDim.x + threadIdx.x;
    if (e < EE) {
        int c = ei[EE + e];
        int p = atomicAdd(&g_offm[c], 1);
        g_perm[p] = e;
    }
}

__global__ void k_build(const int* __restrict__ ei, const float* __restrict__ ew,
                        const float* __restrict__ means, const float* __restrict__ betas) {
    int warp = (blockIdx.x * blockDim.x + threadIdx.x) >> 5;
    int lane = threadIdx.x & 31;
    if (warp >= EE) return;
    int e = g_perm[warp];
    int r = ei[e];
    int c = ei[EE + e];
    float d = ew[e];
    float cut = 0.5f * (cosf(d * 0.628318530717958647692f) + 1.0f);
    if (!(d < 5.0f)) cut = 0.f;
    float ex = __expf(-d);
    size_t ro = (size_t)warp * K1;
    {
        float m = means[lane], b = betas[lane];
        float v = ex - m;
        g_rbf[ro + lane] = __float2half_rn(cut * __expf(-b * v * v));
    }
    int k2 = lane + 32;
    float val2 = 0.f;
    if (k2 < NRBF) {
        float m = means[k2], b = betas[k2];
        float v = ex - m;
        val2 = cut * __expf(-b * v * v);
    }
    g_rbf[ro + k2] = __float2half_rn(val2);
    if (lane == 0) {
        g_cut[warp]  = cut;
        g_cutm[warp] = (r != c) ? cut : 0.f;
        g_srow[warp] = r;
        g_sdst[warp] = c;
    }
}

__global__ void k_gather(const int* __restrict__ z, const float* __restrict__ emb,
                         const float* __restrict__ neemb) {
    int i = blockIdx.x * blockDim.x + threadIdx.x;
    if (i >= NN * HID) return;
    int n = i >> 7, c = i & 127;
    int zi = z[n];
    g_x[i]   = emb[zi * HID + c];
    g_nex[i] = neemb[zi * HID + c];
    g_agg[i] = 0.f;
}

// weight prep
__global__ void k_wprep1(const float* __restrict__ w, int mode, int layers) {
    int i = blockIdx.x * blockDim.x + threadIdx.x;
    if (i >= layers * HID * K1) return;
    int k = i & (K1 - 1);
    int n = (i >> 6) & (HID - 1);
    int l = i >> 13;
    float v = (k < NRBF) ? w[((size_t)l * NRBF + k) * HID + n] : 0.f;
    h16 hi = __float2half_rn(v);
    h16 lo = __float2half_rn(v - __half2float(hi));
    if (mode == 0) { g_w1t_hi[i] = hi; g_w1t_lo[i] = lo; }
    else           { g_npt_hi[i] = hi; g_npt_lo[i] = lo; }
}

__global__ void k_wprep2(const float* __restrict__ w) {
    int i = blockIdx.x * blockDim.x + threadIdx.x;
    if (i >= NLAY * HID * HID) return;
    int k = i & (HID - 1);
    int n = (i >> 7) & (HID - 1);
    int l = i >> 14;
    float v = w[((size_t)l * HID + k) * HID + n];
    h16 hi = __float2half_rn(v);
    g_w2t_hi[i] = hi;
    g_w2t_lo[i] = __float2half_rn(v - __half2float(hi));
}

__global__ void k_wprepAll(const float* __restrict__ necatw, const float* __restrict__ lin1w,
                           const float* __restrict__ lin2w, const float* __restrict__ linw) {
    int slot = blockIdx.x >> 6;
    int i = (blockIdx.x & 63) * 256 + threadIdx.x;
    const float* src;
    if (slot < 2)       src = necatw + (size_t)slot * HID * HID;
    else if (slot < 8)  src = lin1w + (size_t)(slot - 2) * HID * HID;
    else if (slot < 14) src = lin2w + (size_t)(slot - 8) * HID * HID;
    else                src = linw  + (size_t)(slot - 14) * HID * HID;
    int k = i & (HID - 1);
    int n = i >> 7;
    float v = src[k * HID + n];
    h16 hi = __float2half_rn(v);
    g_nwt_hi[(size_t)slot * HID * HID + i] = hi;
    g_nwt_lo[(size_t)slot * HID * HID + i] = __float2half_rn(v - __half2float(hi));
}

// ---------------- warp-MMA helpers (fp16) ----------------
__device__ __forceinline__ void mma16816(float c[4], const unsigned a[4], const unsigned b[2]) {
    asm volatile(
        "mma.sync.aligned.m16n8k16.row.col.f32.f16.f16.f32 "
        "{%0,%1,%2,%3}, {%4,%5,%6,%7}, {%8,%9}, {%0,%1,%2,%3};\n"
        : "+f"(c[0]), "+f"(c[1]), "+f"(c[2]), "+f"(c[3])
        : "r"(a[0]), "r"(a[1]), "r"(a[2]), "r"(a[3]), "r"(b[0]), "r"(b[1]));
}

__device__ __forceinline__ void ldsm4(unsigned r[4], unsigned addr) {
    asm volatile("ldmatrix.sync.aligned.m8n8.x4.shared.b16 {%0,%1,%2,%3}, [%4];"
        : "=r"(r[0]), "=r"(r[1]), "=r"(r[2]), "=r"(r[3]) : "r"(addr));
}

__device__ __forceinline__ unsigned a_addr(unsigned base, int m0, int PB, int lane) {
    int sel = lane >> 3, li = lane & 7;
    return base + (m0 + li + (sel & 1) * 8) * PB + ((sel >> 1) * 8) * 2;
}
__device__ __forceinline__ unsigned b_addr(unsigned base, int n0, int PB, int lane) {
    int sel = lane >> 3, li = lane & 7;
    return base + (n0 + li + (sel >> 1) * 8) * PB + ((sel & 1) * 8) * 2;
}

// 32x32 warp GEMM: acc += A*(Bhi+Blo); A single fp16
template <int KSTEPS, int PB>
__device__ __forceinline__ void wgemm2(unsigned aA, unsigned bHi, unsigned bLo,
                                       float acc[2][4][4]) {
#pragma unroll
    for (int ks = 0; ks < KSTEPS; ks++) {
        unsigned off = ks * 32;
        unsigned a0[4], a1[4], bh0[4], bh1[4], bl0[4], bl1[4];
        ldsm4(a0, aA + off);
        ldsm4(a1, aA + 16 * PB + off);
        ldsm4(bh0, bHi + off);
        ldsm4(bh1, bHi + 16 * PB + off);
        ldsm4(bl0, bLo + off);
        ldsm4(bl1, bLo + 16 * PB + off);
#pragma unroll
        for (int nt = 0; nt < 4; nt++) {
            const unsigned* bh = (nt < 2) ? (bh0 + 2 * nt) : (bh1 + 2 * (nt - 2));
            const unsigned* bl = (nt < 2) ? (bl0 + 2 * nt) : (bl1 + 2 * (nt - 2));
            mma16816(acc[0][nt], a0, bh);
            mma16816(acc[1][nt], a1, bh);
            mma16816(acc[0][nt], a0, bl);
            mma16816(acc[1][nt], a1, bl);
        }
    }
}

// ---------------- cp.async helpers ----------------
__device__ __forceinline__ void cpa16(unsigned saddr, const void* gaddr) {
    asm volatile("cp.async.ca.shared.global [%0], [%1], 16;" :: "r"(saddr), "l"(gaddr));
}
__device__ __forceinline__ void cpa_commit() { asm volatile("cp.async.commit_group;"); }
__device__ __forceinline__ void cpa_wait0()  { asm volatile("cp.async.wait_group 0;"); }
__device__ __forceinline__ void cpa_wait1()  { asm volatile("cp.async.wait_group 1;"); }

// ---------------- fused edge MLP + segmented aggregation (persistent) --------
// Per tile: [wait rbf] -> [stage Hrows via cp.async] -> GEMM1 -> [prefetch next
// rbf] -> GEMM2 -> F (fp16, overlays T) -> [wait Hstage] -> aggregation (smem).
// interaction smem: T/F[0,34816) W2hi[34816) W2lo[69632) rbf[104448,+18432)
//   W1hi[122880) W1lo[141312) Hstage[159744,+67584) misc[227328,+4096) = 231424
// NE smem: F[0,34816) rbf[34816) W1hi[53248) W1lo[71680) Hstage[90112,+67584)
//   misc[157696,+4096) = 161792
template <int NE>
__global__ void __launch_bounds__(512, 1)
k_edge(int layer, const float* __restrict__ b1g, const float* __restrict__ b2g) {
    extern __shared__ __align__(16) char smref[];
    constexpr int R_BYTES  = HID * PR * 2;   // 18432
    constexpr int TF_BYTES = HID * PT * 2;   // 34816
    const int OFF_TF   = 0;
    const int OFF_W2HI = 34816;              // interaction only
    const int OFF_W2LO = 69632;
    const int OFF_R    = NE ? 34816 : 104448;
    const int OFF_W1HI = OFF_R + R_BYTES;
    const int OFF_W1LO = OFF_W1HI + R_BYTES;
    const int OFF_H    = OFF_W1LO + R_BYTES;         // 128 x PH f32
    const int OFF_MISC = OFF_H + HID * PH * 4;
    const int OFF_CUT  = OFF_MISC;          // [2][128] f32
    const int OFF_ROW  = OFF_MISC + 1024;   // [2][128] i32
    const int OFF_DST  = OFF_MISC + 2048;   // [2][128] i32
    const int OFF_B1   = OFF_MISC + 3072;
    const int OFF_B2   = OFF_MISC + 3584;

    h16*  sTF = (h16*)(smref + OFF_TF);
    float* sH  = (float*)(smref + OFF_H);
    float* sB1 = (float*)(smref + OFF_B1);
    float* sB2 = (float*)(smref + OFF_B2);

    int tid = threadIdx.x;
    unsigned sbase = (unsigned)__cvta_generic_to_shared(smref);

    const long NT = EE / 128;
    long tile = blockIdx.x;
    int buf = 0;

    // issue tile-0 rbf + metadata copy
    if (tile < NT) {
        long ebase = tile * 128;
        for (int c = tid; c < 1024; c += 512) {
            int r = c >> 3, ch = c & 7;
            cpa16(sbase + OFF_R + r * (PR * 2) + ch * 16, &g_rbf[(ebase + r) * K1 + ch * 8]);
        }
        if (tid < 32) {
            const float* cs = NE ? g_cutm : g_cut;
            cpa16(sbase + OFF_CUT + tid * 16, cs + ebase + tid * 4);
        } else if (tid < 64) {
            int t = tid - 32;
            cpa16(sbase + OFF_ROW + t * 16, g_srow + ebase + t * 4);
        } else if (tid < 96) {
            int t = tid - 64;
            cpa16(sbase + OFF_DST + t * 16, g_sdst + ebase + t * 4);
        }
    }
    cpa_commit();

    // ---- stage weights once ----
    {
        const unsigned* ghi = (const unsigned*)(NE ? g_npt_hi : (g_w1t_hi + (size_t)layer * HID * K1));
        const unsigned* glo = (const unsigned*)(NE ? g_npt_lo : (g_w1t_lo + (size_t)layer * HID * K1));
        unsigned* shi = (unsigned*)(smref + OFF_W1HI);
        unsigned* slo = (unsigned*)(smref + OFF_W1LO);
        for (int i = tid; i < 128 * 32; i += 512) {
            int r = i >> 5, wd = i & 31;
            shi[r * (PR / 2) + wd] = ghi[i];
            slo[r * (PR / 2) + wd] = glo[i];
        }
    }
    if (!NE) {
        const unsigned* ghi = (const unsigned*)(g_w2t_hi + (size_t)layer * HID * HID);
        const unsigned* glo = (const unsigned*)(g_w2t_lo + (size_t)layer * HID * HID);
        unsigned* shi = (unsigned*)(smref + OFF_W2HI);
        unsigned* slo = (unsigned*)(smref + OFF_W2LO);
        for (int i = tid; i < 128 * 64; i += 512) {
            int r = i >> 6, wd = i & 63;
            shi[r * (PT / 2) + wd] = ghi[i];
            slo[r * (PT / 2) + wd] = glo[i];
        }
    }
    if (tid < 128) {
        sB1[tid] = b1g[tid];
        sB2[tid] = NE ? 0.f : b2g[tid];
    }

    int w = tid >> 5, lane = tid & 31;
    int m0 = (w & 3) * 32, n0 = (w >> 2) * 32;
    int g = lane >> 2, tc = lane & 3;

    unsigned g1a   = a_addr(sbase + OFF_R,    m0, PR * 2, lane);
    unsigned g1bHi = b_addr(sbase + OFF_W1HI, n0, PR * 2, lane);
    unsigned g1bLo = g1bHi + R_BYTES;
    unsigned g2a   = a_addr(sbase + OFF_TF,   m0, PT * 2, lane);
    unsigned g2bHi = b_addr(sbase + OFF_W2HI, n0, PT * 2, lane);
    unsigned g2bLo = g2bHi + TF_BYTES;

    const float* hsrc = NE ? g_nex : g_h;

    for (; tile < NT; tile += gridDim.x, buf ^= 1) {
        cpa_wait0();
        __syncthreads();   // rbf + meta[buf] ready; prev aggregation done

        float* sCut = (float*)(smref + OFF_CUT + buf * 512);
        int*   sRow = (int*)(smref + OFF_ROW + buf * 512);
        int*   sDst = (int*)(smref + OFF_DST + buf * 512);

        // ---- stage gathered h rows into smem (overlaps both GEMMs) ----
        for (int i = tid; i < 4096; i += 512) {
            int e = i >> 5, ch = i & 31;
            cpa16(sbase + OFF_H + e * (PH * 4) + ch * 16,
                  hsrc + (long)sRow[e] * HID + ch * 4);
        }
        cpa_commit();      // group A (Hstage)

        // ---- GEMM1: rbf[128,64] @ W1[64,128] ----
        {
            float acc[2][4][4];
#pragma unroll
            for (int a = 0; a < 2; a++)
#pragma unroll
                for (int b = 0; b < 4; b++)
#pragma unroll
                    for (int c = 0; c < 4; c++) acc[a][b][c] = 0.f;
            wgemm2<K1 / 16, PR * 2>(g1a, g1bHi, g1bLo, acc);

            if (NE) {
                // F = (acc + b1) * cutm -> fp16 TF
#pragma unroll
                for (int mt = 0; mt < 2; mt++) {
                    int ra = m0 + mt * 16 + g, rb2 = ra + 8;
                    float cua = sCut[ra], cub = sCut[rb2];
#pragma unroll
                    for (int nt = 0; nt < 4; nt++) {
                        int col = n0 + nt * 8 + 2 * tc;
                        *(h162*)&sTF[ra * PT + col] = __floats2half2_rn(
                            (acc[mt][nt][0] + sB1[col]) * cua,
                            (acc[mt][nt][1] + sB1[col + 1]) * cua);
                        *(h162*)&sTF[rb2 * PT + col] = __floats2half2_rn(
                            (acc[mt][nt][2] + sB1[col]) * cub,
                            (acc[mt][nt][3] + sB1[col + 1]) * cub);
                    }
                }
            } else {
                // T = silu(acc + b1) -> fp16 TF
#pragma unroll
                for (int mt = 0; mt < 2; mt++) {
                    int ra = m0 + mt * 16 + g, rb2 = ra + 8;
#pragma unroll
                    for (int nt = 0; nt < 4; nt++) {
                        int col = n0 + nt * 8 + 2 * tc;
                        float x0 = acc[mt][nt][0] + sB1[col];
                        float x1 = acc[mt][nt][1] + sB1[col + 1];
                        float x2 = acc[mt][nt][2] + sB1[col];
                        float x3 = acc[mt][nt][3] + sB1[col + 1];
                        x0 = x0 / (1.f + __expf(-x0));
                        x1 = x1 / (1.f + __expf(-x1));
                        x2 = x2 / (1.f + __expf(-x2));
                        x3 = x3 / (1.f + __expf(-x3));
                        *(h162*)&sTF[ra * PT + col]  = __floats2half2_rn(x0, x1);
                        *(h162*)&sTF[rb2 * PT + col] = __floats2half2_rn(x2, x3);
                    }
                }
            }
        }
        __syncthreads();   // rbf dead; T (or F) visible

        // ---- issue next tile's rbf + metadata (group B) ----
        {
            long nxt = tile + gridDim.x;
            if (nxt < NT) {
                long ebase = nxt * 128;
                int nb = buf ^ 1;
                for (int c = tid; c < 1024; c += 512) {
                    int r = c >> 3, ch = c & 7;
                    cpa16(sbase + OFF_R + r * (PR * 2) + ch * 16,
                          &g_rbf[(ebase + r) * K1 + ch * 8]);
                }
                if (tid < 32) {
                    const float* cs = NE ? g_cutm : g_cut;
                    cpa16(sbase + OFF_CUT + nb * 512 + tid * 16, cs + ebase + tid * 4);
                } else if (tid < 64) {
                    int t = tid - 32;
                    cpa16(sbase + OFF_ROW + nb * 512 + t * 16, g_srow + ebase + t * 4);
                } else if (tid < 96) {
                    int t = tid - 64;
                    cpa16(sbase + OFF_DST + nb * 512 + t * 16, g_sdst + ebase + t * 4);
                }
            }
            cpa_commit();
        }

        // ---- GEMM2 (interaction only): T @ W2 -> F overwrites T ----
        if (!NE) {
            float acc[2][4][4];
#pragma unroll
            for (int a = 0; a < 2; a++)
#pragma unroll
                for (int b = 0; b < 4; b++)
#pragma unroll
                    for (int c = 0; c < 4; c++) acc[a][b][c] = 0.f;
            wgemm2<HID / 16, PT * 2>(g2a, g2bHi, g2bLo, acc);
            __syncthreads();   // all T reads done before F overwrite

#pragma unroll
            for (int mt = 0; mt < 2; mt++) {
                int ra = m0 + mt * 16 + g, rb2 = ra + 8;
                float cua = sCut[ra], cub = sCut[rb2];
#pragma unroll
                for (int nt = 0; nt < 4; nt++) {
                    int col = n0 + nt * 8 + 2 * tc;
                    *(h162*)&sTF[ra * PT + col] = __floats2half2_rn(
                        (acc[mt][nt][0] + sB2[col]) * cua,
                        (acc[mt][nt][1] + sB2[col + 1]) * cua);
                    *(h162*)&sTF[rb2 * PT + col] = __floats2half2_rn(
                        (acc[mt][nt][2] + sB2[col]) * cub,
                        (acc[mt][nt][3] + sB2[col + 1]) * cub);
                }
            }
            __syncthreads();   // F visible
        }

        // ---- wait for Hstage (group B may stay in flight), aggregate ----
        cpa_wait1();

        int grp = tid >> 7;
        int f = tid & 127;
        int e0 = grp * 32;
        float accv = 0.f;
        int cur = sDst[e0];
#pragma unroll 1
        for (int b = 0; b < 4; b++) {
#pragma unroll
            for (int j = 0; j < 8; j++) {
                int e = e0 + b * 8 + j;
                int dd = sDst[e];
                if (dd != cur) {
                    atomicAdd(&g_agg[(long)cur * HID + f], accv);
                    accv = 0.f;
                    cur = dd;
                }
                accv = fmaf(sH[e * PH + f], __half2float(sTF[e * PT + f]), accv);
            }
        }
        atomicAdd(&g_agg[(long)cur * HID + f], accv);
    }
}

// ---------------- node-kernel shared pieces (R9, unchanged) ------------------
#define NA_BYTES  (64 * PT * 2)
#define NW_BYTES  (HID * PT * 2)
#define NOFF_A    0
#define NOFF_WA   NA_BYTES
#define NOFF_WB   (NOFF_WA + 2 * NW_BYTES)
#define NOFF_H    (NOFF_WB + 2 * NW_BYTES)
#define NOFF_B    (NOFF_H + NA_BYTES)
#define NSM_TOTAL (NOFF_B + 1024)

__device__ __forceinline__ void stageA_f16(char* smref, int off, const float* src,
                                           int rb, int tid) {
    h16* dst = (h16*)(smref + off);
    for (int i = tid; i < 64 * HID; i += 256) {
        int r = i >> 7, k = i & 127;
        dst[r * PT + k] = __float2half_rn(src[(long)(rb + r) * HID + k]);
    }
}

__device__ __forceinline__ void stageW(char* smref, int off, int slot, int tid) {
    const unsigned* ghi = (const unsigned*)(g_nwt_hi + (size_t)slot * HID * HID);
    const unsigned* glo = (const unsigned*)(g_nwt_lo + (size_t)slot * HID * HID);
    unsigned* shi = (unsigned*)(smref + off);
    unsigned* slo = (unsigned*)(smref + off + NW_BYTES);
    for (int i = tid; i < 128 * 64; i += 256) {
        int r = i >> 6, wd = i & 63;
        shi[r * (PT / 2) + wd] = ghi[i];
        slo[r * (PT / 2) + wd] = glo[i];
    }
}

__global__ void __launch_bounds__(256, 1)
k_nodeNE(const float* __restrict__ necatb) {
    extern __shared__ __align__(16) char smref[];
    float* sBa = (float*)(smref + NOFF_B);

    int tid = threadIdx.x;
    int rb = blockIdx.x * 64;
    unsigned sbase = (unsigned)__cvta_generic_to_shared(smref);

    stageA_f16(smref, NOFF_A, g_x, rb, tid);
    stageW(smref, NOFF_WA, 0, tid);
    stageW(smref, NOFF_WB, 1, tid);
    if (tid < 128) sBa[tid] = necatb[tid];
    __syncthreads();

    int w = tid >> 5, lane = tid & 31;
    int m0 = (w & 1) * 32, n0 = (w >> 1) * 32;
    int g = lane >> 2, tc = lane & 3;

    float acc[2][4][4];
#pragma unroll
    for (int a = 0; a < 2; a++)
#pragma unroll
        for (int b = 0; b < 4; b++)
#pragma unroll
            for (int c = 0; c < 4; c++) acc[a][b][c] = 0.f;

    {
        unsigned aA = a_addr(sbase + NOFF_A, m0, PT * 2, lane);
        unsigned bHi = b_addr(sbase + NOFF_WA, n0, PT * 2, lane);
        wgemm2<HID / 16, PT * 2>(aA, bHi, bHi + NW_BYTES, acc);
    }
    __syncthreads();

    stageA_f16(smref, NOFF_A, g_agg, rb, tid);
    stageW(smref, NOFF_WA, 2, tid);
    __syncthreads();

    {
        float4* za = (float4*)(g_agg + (long)rb * HID);
        for (int i = tid; i < 64 * HID / 4; i += 256) za[i] = make_float4(0.f, 0.f, 0.f, 0.f);
    }

    {
        unsigned aA = a_addr(sbase + NOFF_A, m0, PT * 2, lane);
        unsigned bHi = b_addr(sbase + NOFF_WB, n0, PT * 2, lane);
        wgemm2<HID / 16, PT * 2>(aA, bHi, bHi + NW_BYTES, acc);

        h16* xh = (h16*)(smref + NOFF_H);
#pragma unroll
        for (int mt = 0; mt < 2; mt++) {
#pragma unroll
            for (int dr = 0; dr < 2; dr++) {
                int r = m0 + mt * 16 + g + dr * 8;
                long ro = (long)(rb + r) * HID;
#pragma unroll
                for (int nt = 0; nt < 4; nt++) {
                    int col = n0 + nt * 8 + 2 * tc;
                    float v0 = acc[mt][nt][2 * dr]     + sBa[col];
                    float v1 = acc[mt][nt][2 * dr + 1] + sBa[col + 1];
                    *(float2*)&g_x[ro + col] = make_float2(v0, v1);
                    *(h162*)&xh[r * PT + col] = __floats2half2_rn(v0, v1);
                }
            }
        }
    }
    __syncthreads();

    {
        float acc2[2][4][4];
#pragma unroll
        for (int a = 0; a < 2; a++)
#pragma unroll
            for (int b = 0; b < 4; b++)
#pragma unroll
                for (int c = 0; c < 4; c++) acc2[a][b][c] = 0.f;
        unsigned aA = a_addr(sbase + NOFF_H, m0, PT * 2, lane);
        unsigned bHi = b_addr(sbase + NOFF_WA, n0, PT * 2, lane);
        wgemm2<HID / 16, PT * 2>(aA, bHi, bHi + NW_BYTES, acc2);
#pragma unroll
        for (int mt = 0; mt < 2; mt++) {
#pragma unroll
            for (int dr = 0; dr < 2; dr++) {
                int r = m0 + mt * 16 + g + dr * 8;
                long ro = (long)(rb + r) * HID;
#pragma unroll
                for (int nt = 0; nt < 4; nt++) {
                    int col = n0 + nt * 8 + 2 * tc;
                    *(float2*)&g_h[ro + col] =
                        make_float2(acc2[mt][nt][2 * dr], acc2[mt][nt][2 * dr + 1]);
                }
            }
        }
    }
}

__global__ void __launch_bounds__(256, 1)
k_nodeL(int l, int last, const float* __restrict__ b2g, const float* __restrict__ b3g,
        float* dout) {
    extern __shared__ __align__(16) char smref[];
    float* sB2 = (float*)(smref + NOFF_B);
    float* sB3 = sB2 + 128;

    int tid = threadIdx.x;
    int rb = blockIdx.x * 64;
    unsigned sbase = (unsigned)__cvta_generic_to_shared(smref);

    stageA_f16(smref, NOFF_A, g_agg, rb, tid);
    stageW(smref, NOFF_WA, 8 + l, tid);
    stageW(smref, NOFF_WB, 14 + l, tid);
    if (tid < 128) { sB2[tid] = b2g[tid]; sB3[tid] = b3g[tid]; }
    __syncthreads();

    int w = tid >> 5, lane = tid & 31;
    int m0 = (w & 1) * 32, n0 = (w >> 1) * 32;
    int g = lane >> 2, tc = lane & 3;

    {
        float acc[2][4][4];
#pragma unroll
        for (int a = 0; a < 2; a++)
#pragma unroll
            for (int b = 0; b < 4; b++)
#pragma unroll
                for (int c = 0; c < 4; c++) acc[a][b][c] = 0.f;
        unsigned aA = a_addr(sbase + NOFF_A, m0, PT * 2, lane);
        unsigned bHi = b_addr(sbase + NOFF_WA, n0, PT * 2, lane);
        wgemm2<HID / 16, PT * 2>(aA, bHi, bHi + NW_BYTES, acc);

        h16* sHn = (h16*)(smref + NOFF_H);
#pragma unroll
        for (int mt = 0; mt < 2; mt++) {
            int ra = m0 + mt * 16 + g, rb2 = ra + 8;
#pragma unroll
            for (int nt = 0; nt < 4; nt++) {
                int col = n0 + nt * 8 + 2 * tc;
                float x0 = acc[mt][nt][0] + sB2[col];
                float x1 = acc[mt][nt][1] + sB2[col + 1];
                float x2 = acc[mt][nt][2] + sB2[col];
                float x3 = acc[mt][nt][3] + sB2[col + 1];
                x0 = x0 / (1.f + __expf(-x0));
                x1 = x1 / (1.f + __expf(-x1));
                x2 = x2 / (1.f + __expf(-x2));
                x3 = x3 / (1.f + __expf(-x3));
                *(h162*)&sHn[ra * PT + col]  = __floats2half2_rn(x0, x1);
                *(h162*)&sHn[rb2 * PT + col] = __floats2half2_rn(x2, x3);
            }
        }
    }
    __syncthreads();

    if (!last) {
        stageW(smref, NOFF_WA, 2 + (l + 1), tid);
        float4* za = (float4*)(g_agg + (long)rb * HID);
        for (int i = tid; i < 64 * HID / 4; i += 256) za[i] = make_float4(0.f, 0.f, 0.f, 0.f);
    }

    {
        float acc[2][4][4];
#pragma unroll
        for (int a = 0; a < 2; a++)
#pragma unroll
            for (int b = 0; b < 4; b++)
#pragma unroll
                for (int c = 0; c < 4; c++) acc[a][b][c] = 0.f;
        unsigned aA = a_addr(sbase + NOFF_H, m0, PT * 2, lane);
        unsigned bHi = b_addr(sbase + NOFF_WB, n0, PT * 2, lane);
        wgemm2<HID / 16, PT * 2>(aA, bHi, bHi + NW_BYTES, acc);

        float* out = last ? dout : g_x;
        h16* xh = (h16*)(smref + NOFF_A);
#pragma unroll
        for (int mt = 0; mt < 2; mt++) {
#pragma unroll
            for (int dr = 0; dr < 2; dr++) {
                int r = m0 + mt * 16 + g + dr * 8;
                long ro = (long)(rb + r) * HID;
#pragma unroll
                for (int nt = 0; nt < 4; nt++) {
                    int col = n0 + nt * 8 + 2 * tc;
                    float v0 = acc[mt][nt][2 * dr]     + sB3[col] + g_x[ro + col];
                    float v1 = acc[mt][nt][2 * dr + 1] + sB3[col + 1] + g_x[ro + col + 1];
                    *(float2*)&out[ro + col] = make_float2(v0, v1);
                    if (!last)
                        *(h162*)&xh[r * PT + col] = __floats2half2_rn(v0, v1);
                }
            }
        }
    }
    if (last) return;
    __syncthreads();

    {
        float acc[2][4][4];
#pragma unroll
        for (int a = 0; a < 2; a++)
#pragma unroll
            for (int b = 0; b < 4; b++)
#pragma unroll
                for (int c = 0; c < 4; c++) acc[a][b][c] = 0.f;
        unsigned aA = a_addr(sbase + NOFF_A, m0, PT * 2, lane);
        unsigned bHi = b_addr(sbase + NOFF_WA, n0, PT * 2, lane);
        wgemm2<HID / 16, PT * 2>(aA, bHi, bHi + NW_BYTES, acc);
#pragma unroll
        for (int mt = 0; mt < 2; mt++) {
#pragma unroll
            for (int dr = 0; dr < 2; dr++) {
                int r = m0 + mt * 16 + g + dr * 8;
                long ro = (long)(rb + r) * HID;
#pragma unroll
                for (int nt = 0; nt < 4; nt++) {
                    int col = n0 + nt * 8 + 2 * tc;
                    *(float2*)&g_h[ro + col] =
                        make_float2(acc[mt][nt][2 * dr], acc[mt][nt][2 * dr + 1]);
                }
            }
        }
    }
}

// ---------------- launch ----------------
extern "C" void kernel_launch(void* const* d_in, const int* in_sizes, int n_in,
                              void* d_out, int out_size) {
    const int*   z       = (const int*)d_in[0];
    const int*   ei      = (const int*)d_in[1];
    const float* ew      = (const float*)d_in[2];
    const float* emb     = (const float*)d_in[3];
    const float* neemb   = (const float*)d_in[4];
    const float* neprojw = (const float*)d_in[5];
    const float* neprojb = (const float*)d_in[6];
    const float* necatw  = (const float*)d_in[7];
    const float* necatb  = (const float*)d_in[8];
    const float* means   = (const float*)d_in[9];
    const float* betas   = (const float*)d_in[10];
    const float* mlpw1   = (const float*)d_in[11];
    const float* mlpb1   = (const float*)d_in[12];
    const float* mlpw2   = (const float*)d_in[13];
    const float* mlpb2   = (const float*)d_in[14];
    const float* lin1w   = (const float*)d_in[15];
    const float* lin2w   = (const float*)d_in[16];
    const float* lin2b   = (const float*)d_in[17];
    const float* linw    = (const float*)d_in[18];
    const float* linb    = (const float*)d_in[19];
    float* outp = (float*)d_out;

    const int smI = 104448 + 3 * (HID * PR * 2) + HID * PH * 4 + 4096;   // 231424
    const int smN = 34816 + 3 * (HID * PR * 2) + HID * PH * 4 + 4096 - (HID * PR * 2);  // see below
    // NE: F(34816) + rbf(18432) + W1hi(18432) + W1lo(18432) + H(67584) + misc(4096)
    const int smN2 = 34816 + 3 * 18432 + 67584 + 4096;                    // 161792

    cudaFuncSetAttribute(k_edge<0>, cudaFuncAttributeMaxDynamicSharedMemorySize, smI);
    cudaFuncSetAttribute(k_edge<1>, cudaFuncAttributeMaxDynamicSharedMemorySize, smN2);
    cudaFuncSetAttribute(k_nodeNE,  cudaFuncAttributeMaxDynamicSharedMemorySize, NSM_TOTAL);
    cudaFuncSetAttribute(k_nodeL,   cudaFuncAttributeMaxDynamicSharedMemorySize, NSM_TOTAL);

    // ---- sort edges by destination + precompute per-edge data ----
    k_zero_cnt<<<NN / 256, 256>>>();
    k_hist<<<EE / 256, 256>>>(ei);
    k_scan<<<1, 1024>>>();
    k_place<<<EE / 256, 256>>>(ei);
    k_build<<<EE / 8, 256>>>(ei, ew, means, betas);
    k_gather<<<NN * HID / 256, 256>>>(z, emb, neemb);

    // ---- weight prep ----
    k_wprep1<<<(NLAY * HID * K1 + 255) / 256, 256>>>(mlpw1, 0, NLAY);
    k_wprep1<<<(HID * K1 + 255) / 256, 256>>>(neprojw, 1, 1);
    k_wprep2<<<(NLAY * HID * HID + 255) / 256, 256>>>(mlpw2);
    k_wprepAll<<<NSLOT * 64, 256>>>(necatw, lin1w, lin2w, linw);

    // ---- NeighborEmbedding + initial lin1 ----
    k_edge<1><<<148, 512, smN2>>>(0, neprojb, nullptr);
    k_nodeNE<<<NN / 64, 256, NSM_TOTAL>>>(necatb);

    // ---- interaction layers ----
    for (int l = 0; l < NLAY; l++) {
        k_edge<0><<<148, 512, smI>>>(l, mlpb1 + (size_t)l * HID, mlpb2 + (size_t)l * HID);
        k_nodeL<<<NN / 64, 256, NSM_TOTAL>>>(l, l == NLAY - 1,
                                             lin2b + (size_t)l * HID,
                                             linb + (size_t)l * HID, outp);
    }
    (void)smN;
}

// round 14
// speedup vs baseline: 1.2866x; 1.1790x over previous
#include <cuda_runtime.h>
#include <cuda_fp16.h>
#include <math.h>

// ---------------- problem constants ----------------
#define NN    8192
#define EE    262144
#define HID   128
#define NRBF  50
#define K1    64
#define NLAY  6
#define PR    72           // smem pitch (fp16) for rbf / W1^T
#define PT    136          // smem pitch (fp16) for T / W2^T / node tiles
#define PG    132          // smem pitch (fp16) for F / Hstage in edge kernel
#define NSLOT 20

typedef __half  h16;
typedef __half2 h162;

// ---------------- device scratch ----------------
__device__ __align__(16) h16 g_rbf[(size_t)EE * K1];
__device__ __align__(16) h16 g_w1t_hi[NLAY * HID * K1];
__device__ __align__(16) h16 g_w1t_lo[NLAY * HID * K1];
__device__ __align__(16) h16 g_w2t_hi[NLAY * HID * HID];
__device__ __align__(16) h16 g_w2t_lo[NLAY * HID * HID];
__device__ __align__(16) h16 g_npt_hi[HID * K1];
__device__ __align__(16) h16 g_npt_lo[HID * K1];
__device__ __align__(16) h16 g_nwt_hi[NSLOT * HID * HID];
__device__ __align__(16) h16 g_nwt_lo[NSLOT * HID * HID];
__device__ __align__(16) h16 g_h16 [NN * HID];   // fp16 gather sources
__device__ __align__(16) h16 g_nex16[NN * HID];
__device__ float g_cut[EE];
__device__ float g_cutm[EE];
__device__ int   g_srow[EE];
__device__ int   g_sdst[EE];
__device__ int   g_perm[EE];
__device__ int   g_cnt[NN];
__device__ int   g_offm[NN];
__device__ float g_x  [NN * HID];
__device__ float g_agg[NN * HID];

// ---------------- small helper kernels ----------------
__global__ void k_zero_cnt() {
    int i = blockIdx.x * blockDim.x + threadIdx.x;
    if (i < NN) g_cnt[i] = 0;
}

__global__ void k_hist(const int* __restrict__ ei) {
    int e = blockIdx.x * blockDim.x + threadIdx.x;
    if (e < EE) atomicAdd(&g_cnt[ei[EE + e]], 1);
}

__global__ void k_scan() {
    __shared__ int part[1024];
    int t = threadIdx.x;
    int base = t * 8;
    int loc[8];
    int s = 0;
#pragma unroll
    for (int i = 0; i < 8; i++) { loc[i] = s; s += g_cnt[base + i]; }
    part[t] = s;
    __syncthreads();
    int val = s;
    for (int off = 1; off < 1024; off <<= 1) {
        int v = (t >= off) ? part[t - off] : 0;
        __syncthreads();
        val += v;
        part[t] = val;
        __syncthreads();
    }
    int pre = (t == 0) ? 0 : part[t - 1];
#pragma unroll
    for (int i = 0; i < 8; i++) g_offm[base + i] = pre + loc[i];
}

__global__ void k_place(const int* __restrict__ ei) {
    int e = blockIdx.x * blockDim.x + threadIdx.x;
    if (e < EE) {
        int c = ei[EE + e];
        int p = atomicAdd(&g_offm[c], 1);
        g_perm[p] = e;
    }
}

__global__ void k_build(const int* __restrict__ ei, const float* __restrict__ ew,
                        const float* __restrict__ means, const float* __restrict__ betas) {
    int warp = (blockIdx.x * blockDim.x + threadIdx.x) >> 5;
    int lane = threadIdx.x & 31;
    if (warp >= EE) return;
    int e = g_perm[warp];
    int r = ei[e];
    int c = ei[EE + e];
    float d = ew[e];
    float cut = 0.5f * (cosf(d * 0.628318530717958647692f) + 1.0f);
    if (!(d < 5.0f)) cut = 0.f;
    float ex = __expf(-d);
    size_t ro = (size_t)warp * K1;
    {
        float m = means[lane], b = betas[lane];
        float v = ex - m;
        g_rbf[ro + lane] = __float2half_rn(cut * __expf(-b * v * v));
    }
    int k2 = lane + 32;
    float val2 = 0.f;
    if (k2 < NRBF) {
        float m = means[k2], b = betas[k2];
        float v = ex - m;
        val2 = cut * __expf(-b * v * v);
    }
    g_rbf[ro + k2] = __float2half_rn(val2);
    if (lane == 0) {
        g_cut[warp]  = cut;
        g_cutm[warp] = (r != c) ? cut : 0.f;
        g_srow[warp] = r;
        g_sdst[warp] = c;
    }
}

__global__ void k_gather(const int* __restrict__ z, const float* __restrict__ emb,
                         const float* __restrict__ neemb) {
    int i = blockIdx.x * blockDim.x + threadIdx.x;
    if (i >= NN * HID) return;
    int n = i >> 7, c = i & 127;
    int zi = z[n];
    g_x[i]     = emb[zi * HID + c];
    g_nex16[i] = __float2half_rn(neemb[zi * HID + c]);
    g_agg[i]   = 0.f;
}

// weight prep
__global__ void k_wprep1(const float* __restrict__ w, int mode, int layers) {
    int i = blockIdx.x * blockDim.x + threadIdx.x;
    if (i >= layers * HID * K1) return;
    int k = i & (K1 - 1);
    int n = (i >> 6) & (HID - 1);
    int l = i >> 13;
    float v = (k < NRBF) ? w[((size_t)l * NRBF + k) * HID + n] : 0.f;
    h16 hi = __float2half_rn(v);
    h16 lo = __float2half_rn(v - __half2float(hi));
    if (mode == 0) { g_w1t_hi[i] = hi; g_w1t_lo[i] = lo; }
    else           { g_npt_hi[i] = hi; g_npt_lo[i] = lo; }
}

__global__ void k_wprep2(const float* __restrict__ w) {
    int i = blockIdx.x * blockDim.x + threadIdx.x;
    if (i >= NLAY * HID * HID) return;
    int k = i & (HID - 1);
    int n = (i >> 7) & (HID - 1);
    int l = i >> 14;
    float v = w[((size_t)l * HID + k) * HID + n];
    h16 hi = __float2half_rn(v);
    g_w2t_hi[i] = hi;
    g_w2t_lo[i] = __float2half_rn(v - __half2float(hi));
}

__global__ void k_wprepAll(const float* __restrict__ necatw, const float* __restrict__ lin1w,
                           const float* __restrict__ lin2w, const float* __restrict__ linw) {
    int slot = blockIdx.x >> 6;
    int i = (blockIdx.x & 63) * 256 + threadIdx.x;
    const float* src;
    if (slot < 2)       src = necatw + (size_t)slot * HID * HID;
    else if (slot < 8)  src = lin1w + (size_t)(slot - 2) * HID * HID;
    else if (slot < 14) src = lin2w + (size_t)(slot - 8) * HID * HID;
    else                src = linw  + (size_t)(slot - 14) * HID * HID;
    int k = i & (HID - 1);
    int n = i >> 7;
    float v = src[k * HID + n];
    h16 hi = __float2half_rn(v);
    g_nwt_hi[(size_t)slot * HID * HID + i] = hi;
    g_nwt_lo[(size_t)slot * HID * HID + i] = __float2half_rn(v - __half2float(hi));
}

// ---------------- warp-MMA helpers (fp16) ----------------
__device__ __forceinline__ void mma16816(float c[4], const unsigned a[4], const unsigned b[2]) {
    asm volatile(
        "mma.sync.aligned.m16n8k16.row.col.f32.f16.f16.f32 "
        "{%0,%1,%2,%3}, {%4,%5,%6,%7}, {%8,%9}, {%0,%1,%2,%3};\n"
        : "+f"(c[0]), "+f"(c[1]), "+f"(c[2]), "+f"(c[3])
        : "r"(a[0]), "r"(a[1]), "r"(a[2]), "r"(a[3]), "r"(b[0]), "r"(b[1]));
}

__device__ __forceinline__ void ldsm4(unsigned r[4], unsigned addr) {
    asm volatile("ldmatrix.sync.aligned.m8n8.x4.shared.b16 {%0,%1,%2,%3}, [%4];"
        : "=r"(r[0]), "=r"(r[1]), "=r"(r[2]), "=r"(r[3]) : "r"(addr));
}

__device__ __forceinline__ unsigned a_addr(unsigned base, int m0, int PB, int lane) {
    int sel = lane >> 3, li = lane & 7;
    return base + (m0 + li + (sel & 1) * 8) * PB + ((sel >> 1) * 8) * 2;
}
__device__ __forceinline__ unsigned b_addr(unsigned base, int n0, int PB, int lane) {
    int sel = lane >> 3, li = lane & 7;
    return base + (n0 + li + (sel >> 1) * 8) * PB + ((sel & 1) * 8) * 2;
}

// 32x32 warp GEMM: acc += A*(Bhi+Blo); A single fp16
template <int KSTEPS, int PB>
__device__ __forceinline__ void wgemm2(unsigned aA, unsigned bHi, unsigned bLo,
                                       float acc[2][4][4]) {
#pragma unroll
    for (int ks = 0; ks < KSTEPS; ks++) {
        unsigned off = ks * 32;
        unsigned a0[4], a1[4], bh0[4], bh1[4], bl0[4], bl1[4];
        ldsm4(a0, aA + off);
        ldsm4(a1, aA + 16 * PB + off);
        ldsm4(bh0, bHi + off);
        ldsm4(bh1, bHi + 16 * PB + off);
        ldsm4(bl0, bLo + off);
        ldsm4(bl1, bLo + 16 * PB + off);
#pragma unroll
        for (int nt = 0; nt < 4; nt++) {
            const unsigned* bh = (nt < 2) ? (bh0 + 2 * nt) : (bh1 + 2 * (nt - 2));
            const unsigned* bl = (nt < 2) ? (bl0 + 2 * nt) : (bl1 + 2 * (nt - 2));
            mma16816(acc[0][nt], a0, bh);
            mma16816(acc[1][nt], a1, bh);
            mma16816(acc[0][nt], a0, bl);
            mma16816(acc[1][nt], a1, bl);
        }
    }
}

// ---------------- cp.async helpers ----------------
__device__ __forceinline__ void cpa16(unsigned saddr, const void* gaddr) {
    asm volatile("cp.async.ca.shared.global [%0], [%1], 16;" :: "r"(saddr), "l"(gaddr));
}
__device__ __forceinline__ void cpa8(unsigned saddr, const void* gaddr) {
    asm volatile("cp.async.ca.shared.global [%0], [%1], 8;" :: "r"(saddr), "l"(gaddr));
}
__device__ __forceinline__ void cpa_commit() { asm volatile("cp.async.commit_group;"); }
__device__ __forceinline__ void cpa_wait0()  { asm volatile("cp.async.wait_group 0;"); }
__device__ __forceinline__ void cpa_wait1()  { asm volatile("cp.async.wait_group 1;"); }

__device__ __forceinline__ float fsilu(float x) {
    return __fdividef(x, 1.f + __expf(-x));
}

// ---------------- fused edge MLP + segmented aggregation (persistent) --------
// interaction smem: T[0,34816) W2hi[34816) W2lo[69632) rbf[104448,+18432)
//   W1hi[122880) W1lo[141312) H16[159744,+33792) F16[193536,+33792)
//   misc[227328,+4096) = 231424
// NE smem: F16[0,33792) rbf[33792) W1hi[52224) W1lo[70656) H16[89088,+33792)
//   misc[122880,+4096) = 126976
template <int NE>
__global__ void __launch_bounds__(512, 1)
k_edge(int layer, const float* __restrict__ b1g, const float* __restrict__ b2g) {
    extern __shared__ __align__(16) char smref[];
    constexpr int R_BYTES  = HID * PR * 2;   // 18432
    constexpr int TF_BYTES = HID * PT * 2;   // 34816
    const int OFF_T    = 0;                  // interaction only
    const int OFF_W2HI = 34816;
    const int OFF_W2LO = 69632;
    const int OFF_R    = NE ? 33792 : 104448;
    const int OFF_W1HI = OFF_R + R_BYTES;
    const int OFF_W1LO = OFF_W1HI + R_BYTES;
    const int OFF_H    = NE ? (OFF_W1LO + R_BYTES) : 159744;
    const int OFF_F    = NE ? 0 : 193536;
    const int OFF_MISC = NE ? 122880 : 227328;
    const int OFF_CUT  = OFF_MISC;          // [2][128] f32
    const int OFF_ROW  = OFF_MISC + 1024;   // [2][128] i32
    const int OFF_DST  = OFF_MISC + 2048;   // [2][128] i32
    const int OFF_B1   = OFF_MISC + 3072;
    const int OFF_B2   = OFF_MISC + 3584;

    h16*  sT   = (h16*)(smref + OFF_T);
    h16*  sF16 = (h16*)(smref + OFF_F);
    h16*  sH16 = (h16*)(smref + OFF_H);
    float* sB1 = (float*)(smref + OFF_B1);
    float* sB2 = (float*)(smref + OFF_B2);

    int tid = threadIdx.x;
    unsigned sbase = (unsigned)__cvta_generic_to_shared(smref);

    const long NT = EE / 128;
    long tile = blockIdx.x;
    int buf = 0;

    // issue tile-0 rbf + metadata copy
    if (tile < NT) {
        long ebase = tile * 128;
        for (int c = tid; c < 1024; c += 512) {
            int r = c >> 3, ch = c & 7;
            cpa16(sbase + OFF_R + r * (PR * 2) + ch * 16, &g_rbf[(ebase + r) * K1 + ch * 8]);
        }
        if (tid < 32) {
            const float* cs = NE ? g_cutm : g_cut;
            cpa16(sbase + OFF_CUT + tid * 16, cs + ebase + tid * 4);
        } else if (tid < 64) {
            int t = tid - 32;
            cpa16(sbase + OFF_ROW + t * 16, g_srow + ebase + t * 4);
        } else if (tid < 96) {
            int t = tid - 64;
            cpa16(sbase + OFF_DST + t * 16, g_sdst + ebase + t * 4);
        }
    }
    cpa_commit();

    // ---- stage weights once ----
    {
        const unsigned* ghi = (const unsigned*)(NE ? g_npt_hi : (g_w1t_hi + (size_t)layer * HID * K1));
        const unsigned* glo = (const unsigned*)(NE ? g_npt_lo : (g_w1t_lo + (size_t)layer * HID * K1));
        unsigned* shi = (unsigned*)(smref + OFF_W1HI);
        unsigned* slo = (unsigned*)(smref + OFF_W1LO);
        for (int i = tid; i < 128 * 32; i += 512) {
            int r = i >> 5, wd = i & 31;
            shi[r * (PR / 2) + wd] = ghi[i];
            slo[r * (PR / 2) + wd] = glo[i];
        }
    }
    if (!NE) {
        const unsigned* ghi = (const unsigned*)(g_w2t_hi + (size_t)layer * HID * HID);
        const unsigned* glo = (const unsigned*)(g_w2t_lo + (size_t)layer * HID * HID);
        unsigned* shi = (unsigned*)(smref + OFF_W2HI);
        unsigned* slo = (unsigned*)(smref + OFF_W2LO);
        for (int i = tid; i < 128 * 64; i += 512) {
            int r = i >> 6, wd = i & 63;
            shi[r * (PT / 2) + wd] = ghi[i];
            slo[r * (PT / 2) + wd] = glo[i];
        }
    }
    if (tid < 128) {
        sB1[tid] = b1g[tid];
        sB2[tid] = NE ? 0.f : b2g[tid];
    }

    int w = tid >> 5, lane = tid & 31;
    int m0 = (w & 3) * 32, n0 = (w >> 2) * 32;
    int g = lane >> 2, tc = lane & 3;

    unsigned g1a   = a_addr(sbase + OFF_R,    m0, PR * 2, lane);
    unsigned g1bHi = b_addr(sbase + OFF_W1HI, n0, PR * 2, lane);
    unsigned g1bLo = g1bHi + R_BYTES;
    unsigned g2a   = a_addr(sbase + OFF_T,    m0, PT * 2, lane);
    unsigned g2bHi = b_addr(sbase + OFF_W2HI, n0, PT * 2, lane);
    unsigned g2bLo = g2bHi + TF_BYTES;

    const h16* hsrc = NE ? g_nex16 : g_h16;

    for (; tile < NT; tile += gridDim.x, buf ^= 1) {
        cpa_wait0();
        __syncthreads();   // rbf + meta[buf] ready; prev aggregation done (H/F free)

        float* sCut = (float*)(smref + OFF_CUT + buf * 512);
        int*   sRow = (int*)(smref + OFF_ROW + buf * 512);
        int*   sDst = (int*)(smref + OFF_DST + buf * 512);

        // ---- stage gathered h rows (fp16) into smem — 8B cp.async (pitch 264B)
        for (int i = tid; i < 4096; i += 512) {
            int e = i >> 5, ch = i & 31;
            cpa8(sbase + OFF_H + e * (PG * 2) + ch * 8,
                 hsrc + (long)sRow[e] * HID + ch * 4);
        }
        cpa_commit();      // group A (Hstage)

        // ---- GEMM1: rbf[128,64] @ W1[64,128] ----
        {
            float acc[2][4][4];
#pragma unroll
            for (int a = 0; a < 2; a++)
#pragma unroll
                for (int b = 0; b < 4; b++)
#pragma unroll
                    for (int c = 0; c < 4; c++) acc[a][b][c] = 0.f;
            wgemm2<K1 / 16, PR * 2>(g1a, g1bHi, g1bLo, acc);

            if (NE) {
                // F = (acc + b1) * cutm -> fp16 F
#pragma unroll
                for (int mt = 0; mt < 2; mt++) {
                    int ra = m0 + mt * 16 + g, rb2 = ra + 8;
                    float cua = sCut[ra], cub = sCut[rb2];
#pragma unroll
                    for (int nt = 0; nt < 4; nt++) {
                        int col = n0 + nt * 8 + 2 * tc;
                        *(h162*)&sF16[ra * PG + col] = __floats2half2_rn(
                            (acc[mt][nt][0] + sB1[col]) * cua,
                            (acc[mt][nt][1] + sB1[col + 1]) * cua);
                        *(h162*)&sF16[rb2 * PG + col] = __floats2half2_rn(
                            (acc[mt][nt][2] + sB1[col]) * cub,
                            (acc[mt][nt][3] + sB1[col + 1]) * cub);
                    }
                }
            } else {
                // T = silu(acc + b1) -> fp16 T
#pragma unroll
                for (int mt = 0; mt < 2; mt++) {
                    int ra = m0 + mt * 16 + g, rb2 = ra + 8;
#pragma unroll
                    for (int nt = 0; nt < 4; nt++) {
                        int col = n0 + nt * 8 + 2 * tc;
                        float x0 = fsilu(acc[mt][nt][0] + sB1[col]);
                        float x1 = fsilu(acc[mt][nt][1] + sB1[col + 1]);
                        float x2 = fsilu(acc[mt][nt][2] + sB1[col]);
                        float x3 = fsilu(acc[mt][nt][3] + sB1[col + 1]);
                        *(h162*)&sT[ra * PT + col]  = __floats2half2_rn(x0, x1);
                        *(h162*)&sT[rb2 * PT + col] = __floats2half2_rn(x2, x3);
                    }
                }
            }
        }
        __syncthreads();   // rbf dead; T (or F) visible

        // ---- issue next tile's rbf + metadata (group B) ----
        {
            long nxt = tile + gridDim.x;
            if (nxt < NT) {
                long ebase = nxt * 128;
                int nb = buf ^ 1;
                for (int c = tid; c < 1024; c += 512) {
                    int r = c >> 3, ch = c & 7;
                    cpa16(sbase + OFF_R + r * (PR * 2) + ch * 16,
                          &g_rbf[(ebase + r) * K1 + ch * 8]);
                }
                if (tid < 32) {
                    const float* cs = NE ? g_cutm : g_cut;
                    cpa16(sbase + OFF_CUT + nb * 512 + tid * 16, cs + ebase + tid * 4);
                } else if (tid < 64) {
                    int t = tid - 32;
                    cpa16(sbase + OFF_ROW + nb * 512 + t * 16, g_srow + ebase + t * 4);
                } else if (tid < 96) {
                    int t = tid - 64;
                    cpa16(sbase + OFF_DST + nb * 512 + t * 16, g_sdst + ebase + t * 4);
                }
            }
            cpa_commit();
        }

        // ---- GEMM2 (interaction only): T @ W2 -> F (separate region) ----
        if (!NE) {
            float acc[2][4][4];
#pragma unroll
            for (int a = 0; a < 2; a++)
#pragma unroll
                for (int b = 0; b < 4; b++)
#pragma unroll
                    for (int c = 0; c < 4; c++) acc[a][b][c] = 0.f;
            wgemm2<HID / 16, PT * 2>(g2a, g2bHi, g2bLo, acc);
            // F separate from T -> no WAR sync needed before writing
#pragma unroll
            for (int mt = 0; mt < 2; mt++) {
                int ra = m0 + mt * 16 + g, rb2 = ra + 8;
                float cua = sCut[ra], cub = sCut[rb2];
#pragma unroll
                for (int nt = 0; nt < 4; nt++) {
                    int col = n0 + nt * 8 + 2 * tc;
                    *(h162*)&sF16[ra * PG + col] = __floats2half2_rn(
                        (acc[mt][nt][0] + sB2[col]) * cua,
                        (acc[mt][nt][1] + sB2[col + 1]) * cua);
                    *(h162*)&sF16[rb2 * PG + col] = __floats2half2_rn(
                        (acc[mt][nt][2] + sB2[col]) * cub,
                        (acc[mt][nt][3] + sB2[col + 1]) * cub);
                }
            }
        }
        __syncthreads();   // F visible

        // ---- wait for Hstage (group B may stay in flight), aggregate ----
        cpa_wait1();

        // 8 groups x 64 threads; each thread: channel pair, 16 edges
        int grp = tid >> 6;
        int f2 = tid & 63;
        int c0 = 2 * f2;
        int e0 = grp * 16;
        float a0 = 0.f, a1 = 0.f;
        int cur = sDst[e0];
#pragma unroll 4
        for (int j = 0; j < 16; j++) {
            int e = e0 + j;
            int dd = sDst[e];
            if (dd != cur) {
                atomicAdd(&g_agg[(long)cur * HID + c0], a0);
                atomicAdd(&g_agg[(long)cur * HID + c0 + 1], a1);
                a0 = a1 = 0.f;
                cur = dd;
            }
            float2 hf = __half22float2(*(const h162*)&sH16[e * PG + c0]);
            float2 ff = __half22float2(*(const h162*)&sF16[e * PG + c0]);
            a0 = fmaf(hf.x, ff.x, a0);
            a1 = fmaf(hf.y, ff.y, a1);
        }
        atomicAdd(&g_agg[(long)cur * HID + c0], a0);
        atomicAdd(&g_agg[(long)cur * HID + c0 + 1], a1);
    }
}

// ---------------- node-kernel shared pieces ----------------
#define NA_BYTES  (64 * PT * 2)
#define NW_BYTES  (HID * PT * 2)
#define NOFF_A    0
#define NOFF_WA   NA_BYTES
#define NOFF_WB   (NOFF_WA + 2 * NW_BYTES)
#define NOFF_H    (NOFF_WB + 2 * NW_BYTES)
#define NOFF_B    (NOFF_H + NA_BYTES)
#define NSM_TOTAL (NOFF_B + 1024)

__device__ __forceinline__ void stageA_f16(char* smref, int off, const float* src,
                                           int rb, int tid) {
    h16* dst = (h16*)(smref + off);
    for (int i = tid; i < 64 * HID; i += 256) {
        int r = i >> 7, k = i & 127;
        dst[r * PT + k] = __float2half_rn(src[(long)(rb + r) * HID + k]);
    }
}

__device__ __forceinline__ void stageW(char* smref, int off, int slot, int tid) {
    const unsigned* ghi = (const unsigned*)(g_nwt_hi + (size_t)slot * HID * HID);
    const unsigned* glo = (const unsigned*)(g_nwt_lo + (size_t)slot * HID * HID);
    unsigned* shi = (unsigned*)(smref + off);
    unsigned* slo = (unsigned*)(smref + off + NW_BYTES);
    for (int i = tid; i < 128 * 64; i += 256) {
        int r = i >> 6, wd = i & 63;
        shi[r * (PT / 2) + wd] = ghi[i];
        slo[r * (PT / 2) + wd] = glo[i];
    }
}

// ---------------- NE node kernel: x = x@Wtop + agg@Wbot + b; h = x@lin1[0] ----
__global__ void __launch_bounds__(256, 1)
k_nodeNE(const float* __restrict__ necatb) {
    extern __shared__ __align__(16) char smref[];
    float* sBa = (float*)(smref + NOFF_B);

    int tid = threadIdx.x;
    int rb = blockIdx.x * 64;
    unsigned sbase = (unsigned)__cvta_generic_to_shared(smref);

    stageA_f16(smref, NOFF_A, g_x, rb, tid);
    stageW(smref, NOFF_WA, 0, tid);
    stageW(smref, NOFF_WB, 1, tid);
    if (tid < 128) sBa[tid] = necatb[tid];
    __syncthreads();

    int w = tid >> 5, lane = tid & 31;
    int m0 = (w & 1) * 32, n0 = (w >> 1) * 32;
    int g = lane >> 2, tc = lane & 3;

    float acc[2][4][4];
#pragma unroll
    for (int a = 0; a < 2; a++)
#pragma unroll
        for (int b = 0; b < 4; b++)
#pragma unroll
            for (int c = 0; c < 4; c++) acc[a][b][c] = 0.f;

    {
        unsigned aA = a_addr(sbase + NOFF_A, m0, PT * 2, lane);
        unsigned bHi = b_addr(sbase + NOFF_WA, n0, PT * 2, lane);
        wgemm2<HID / 16, PT * 2>(aA, bHi, bHi + NW_BYTES, acc);
    }
    __syncthreads();

    stageA_f16(smref, NOFF_A, g_agg, rb, tid);
    stageW(smref, NOFF_WA, 2, tid);
    __syncthreads();

    {
        float4* za = (float4*)(g_agg + (long)rb * HID);
        for (int i = tid; i < 64 * HID / 4; i += 256) za[i] = make_float4(0.f, 0.f, 0.f, 0.f);
    }

    {
        unsigned aA = a_addr(sbase + NOFF_A, m0, PT * 2, lane);
        unsigned bHi = b_addr(sbase + NOFF_WB, n0, PT * 2, lane);
        wgemm2<HID / 16, PT * 2>(aA, bHi, bHi + NW_BYTES, acc);

        h16* xh = (h16*)(smref + NOFF_H);
#pragma unroll
        for (int mt = 0; mt < 2; mt++) {
#pragma unroll
            for (int dr = 0; dr < 2; dr++) {
                int r = m0 + mt * 16 + g + dr * 8;
                long ro = (long)(rb + r) * HID;
#pragma unroll
                for (int nt = 0; nt < 4; nt++) {
                    int col = n0 + nt * 8 + 2 * tc;
                    float v0 = acc[mt][nt][2 * dr]     + sBa[col];
                    float v1 = acc[mt][nt][2 * dr + 1] + sBa[col + 1];
                    *(float2*)&g_x[ro + col] = make_float2(v0, v1);
                    *(h162*)&xh[r * PT + col] = __floats2half2_rn(v0, v1);
                }
            }
        }
    }
    __syncthreads();

    // GEMM C: h = x @ lin1[0]  -> g_h16
    {
        float acc2[2][4][4];
#pragma unroll
        for (int a = 0; a < 2; a++)
#pragma unroll
            for (int b = 0; b < 4; b++)
#pragma unroll
                for (int c = 0; c < 4; c++) acc2[a][b][c] = 0.f;
        unsigned aA = a_addr(sbase + NOFF_H, m0, PT * 2, lane);
        unsigned bHi = b_addr(sbase + NOFF_WA, n0, PT * 2, lane);
        wgemm2<HID / 16, PT * 2>(aA, bHi, bHi + NW_BYTES, acc2);
#pragma unroll
        for (int mt = 0; mt < 2; mt++) {
#pragma unroll
            for (int dr = 0; dr < 2; dr++) {
                int r = m0 + mt * 16 + g + dr * 8;
                long ro = (long)(rb + r) * HID;
#pragma unroll
                for (int nt = 0; nt < 4; nt++) {
                    int col = n0 + nt * 8 + 2 * tc;
                    *(h162*)&g_h16[ro + col] =
                        __floats2half2_rn(acc2[mt][nt][2 * dr], acc2[mt][nt][2 * dr + 1]);
                }
            }
        }
    }
}

// ---------------- layer node kernel ----------------
__global__ void __launch_bounds__(256, 1)
k_nodeL(int l, int last, const float* __restrict__ b2g, const float* __restrict__ b3g,
        float* dout) {
    extern __shared__ __align__(16) char smref[];
    float* sB2 = (float*)(smref + NOFF_B);
    float* sB3 = sB2 + 128;

    int tid = threadIdx.x;
    int rb = blockIdx.x * 64;
    unsigned sbase = (unsigned)__cvta_generic_to_shared(smref);

    stageA_f16(smref, NOFF_A, g_agg, rb, tid);
    stageW(smref, NOFF_WA, 8 + l, tid);
    stageW(smref, NOFF_WB, 14 + l, tid);
    if (tid < 128) { sB2[tid] = b2g[tid]; sB3[tid] = b3g[tid]; }
    __syncthreads();

    int w = tid >> 5, lane = tid & 31;
    int m0 = (w & 1) * 32, n0 = (w >> 1) * 32;
    int g = lane >> 2, tc = lane & 3;

    {
        float acc[2][4][4];
#pragma unroll
        for (int a = 0; a < 2; a++)
#pragma unroll
            for (int b = 0; b < 4; b++)
#pragma unroll
                for (int c = 0; c < 4; c++) acc[a][b][c] = 0.f;
        unsigned aA = a_addr(sbase + NOFF_A, m0, PT * 2, lane);
        unsigned bHi = b_addr(sbase + NOFF_WA, n0, PT * 2, lane);
        wgemm2<HID / 16, PT * 2>(aA, bHi, bHi + NW_BYTES, acc);

        h16* sHn = (h16*)(smref + NOFF_H);
#pragma unroll
        for (int mt = 0; mt < 2; mt++) {
            int ra = m0 + mt * 16 + g, rb2 = ra + 8;
#pragma unroll
            for (int nt = 0; nt < 4; nt++) {
                int col = n0 + nt * 8 + 2 * tc;
                float x0 = fsilu(acc[mt][nt][0] + sB2[col]);
                float x1 = fsilu(acc[mt][nt][1] + sB2[col + 1]);
                float x2 = fsilu(acc[mt][nt][2] + sB2[col]);
                float x3 = fsilu(acc[mt][nt][3] + sB2[col + 1]);
                *(h162*)&sHn[ra * PT + col]  = __floats2half2_rn(x0, x1);
                *(h162*)&sHn[rb2 * PT + col] = __floats2half2_rn(x2, x3);
            }
        }
    }
    __syncthreads();

    if (!last) {
        stageW(smref, NOFF_WA, 2 + (l + 1), tid);
        float4* za = (float4*)(g_agg + (long)rb * HID);
        for (int i = tid; i < 64 * HID / 4; i += 256) za[i] = make_float4(0.f, 0.f, 0.f, 0.f);
    }

    {
        float acc[2][4][4];
#pragma unroll
        for (int a = 0; a < 2; a++)
#pragma unroll
            for (int b = 0; b < 4; b++)
#pragma unroll
                for (int c = 0; c < 4; c++) acc[a][b][c] = 0.f;
        unsigned aA = a_addr(sbase + NOFF_H, m0, PT * 2, lane);
        unsigned bHi = b_addr(sbase + NOFF_WB, n0, PT * 2, lane);
        wgemm2<HID / 16, PT * 2>(aA, bHi, bHi + NW_BYTES, acc);

        float* out = last ? dout : g_x;
        h16* xh = (h16*)(smref + NOFF_A);
#pragma unroll
        for (int mt = 0; mt < 2; mt++) {
#pragma unroll
            for (int dr = 0; dr < 2; dr++) {
                int r = m0 + mt * 16 + g + dr * 8;
                long ro = (long)(rb + r) * HID;
#pragma unroll
                for (int nt = 0; nt < 4; nt++) {
                    int col = n0 + nt * 8 + 2 * tc;
                    float v0 = acc[mt][nt][2 * dr]     + sB3[col] + g_x[ro + col];
                    float v1 = acc[mt][nt][2 * dr + 1] + sB3[col + 1] + g_x[ro + col + 1];
                    *(float2*)&out[ro + col] = make_float2(v0, v1);
                    if (!last)
                        *(h162*)&xh[r * PT + col] = __floats2half2_rn(v0, v1);
                }
            }
        }
    }
    if (last) return;
    __syncthreads();

    // GEMM C: h = x @ lin1[l+1]  -> g_h16
    {
        float acc[2][4][4];
#pragma unroll
        for (int a = 0; a < 2; a++)
#pragma unroll
            for (int b = 0; b < 4; b++)
#pragma unroll
                for (int c = 0; c < 4; c++) acc[a][b][c] = 0.f;
        unsigned aA = a_addr(sbase + NOFF_A, m0, PT * 2, lane);
        unsigned bHi = b_addr(sbase + NOFF_WA, n0, PT * 2, lane);
        wgemm2<HID / 16, PT * 2>(aA, bHi, bHi + NW_BYTES, acc);
#pragma unroll
        for (int mt = 0; mt < 2; mt++) {
#pragma unroll
            for (int dr = 0; dr < 2; dr++) {
                int r = m0 + mt * 16 + g + dr * 8;
                long ro = (long)(rb + r) * HID;
#pragma unroll
                for (int nt = 0; nt < 4; nt++) {
                    int col = n0 + nt * 8 + 2 * tc;
                    *(h162*)&g_h16[ro + col] =
                        __floats2half2_rn(acc[mt][nt][2 * dr], acc[mt][nt][2 * dr + 1]);
                }
            }
        }
    }
}

// ---------------- launch ----------------
extern "C" void kernel_launch(void* const* d_in, const int* in_sizes, int n_in,
                              void* d_out, int out_size) {
    const int*   z       = (const int*)d_in[0];
    const int*   ei      = (const int*)d_in[1];
    const float* ew      = (const float*)d_in[2];
    const float* emb     = (const float*)d_in[3];
    const float* neemb   = (const float*)d_in[4];
    const float* neprojw = (const float*)d_in[5];
    const float* neprojb = (const float*)d_in[6];
    const float* necatw  = (const float*)d_in[7];
    const float* necatb  = (const float*)d_in[8];
    const float* means   = (const float*)d_in[9];
    const float* betas   = (const float*)d_in[10];
    const float* mlpw1   = (const float*)d_in[11];
    const float* mlpb1   = (const float*)d_in[12];
    const float* mlpw2   = (const float*)d_in[13];
    const float* mlpb2   = (const float*)d_in[14];
    const float* lin1w   = (const float*)d_in[15];
    const float* lin2w   = (const float*)d_in[16];
    const float* lin2b   = (const float*)d_in[17];
    const float* linw    = (const float*)d_in[18];
    const float* linb    = (const float*)d_in[19];
    float* outp = (float*)d_out;

    const int smI = 227328 + 4096;   // 231424
    const int smN = 122880 + 4096;   // 126976

    cudaFuncSetAttribute(k_edge<0>, cudaFuncAttributeMaxDynamicSharedMemorySize, smI);
    cudaFuncSetAttribute(k_edge<1>, cudaFuncAttributeMaxDynamicSharedMemorySize, smN);
    cudaFuncSetAttribute(k_nodeNE,  cudaFuncAttributeMaxDynamicSharedMemorySize, NSM_TOTAL);
    cudaFuncSetAttribute(k_nodeL,   cudaFuncAttributeMaxDynamicSharedMemorySize, NSM_TOTAL);

    // ---- sort edges by destination + precompute per-edge data ----
    k_zero_cnt<<<NN / 256, 256>>>();
    k_hist<<<EE / 256, 256>>>(ei);
    k_scan<<<1, 1024>>>();
    k_place<<<EE / 256, 256>>>(ei);
    k_build<<<EE / 8, 256>>>(ei, ew, means, betas);
    k_gather<<<NN * HID / 256, 256>>>(z, emb, neemb);

    // ---- weight prep ----
    k_wprep1<<<(NLAY * HID * K1 + 255) / 256, 256>>>(mlpw1, 0, NLAY);
    k_wprep1<<<(HID * K1 + 255) / 256, 256>>>(neprojw, 1, 1);
    k_wprep2<<<(NLAY * HID * HID + 255) / 256, 256>>>(mlpw2);
    k_wprepAll<<<NSLOT * 64, 256>>>(necatw, lin1w, lin2w, linw);

    // ---- NeighborEmbedding + initial lin1 ----
    k_edge<1><<<148, 512, smN>>>(0, neprojb, nullptr);
    k_nodeNE<<<NN / 64, 256, NSM_TOTAL>>>(necatb);

    // ---- interaction layers ----
    for (int l = 0; l < NLAY; l++) {
        k_edge<0><<<148, 512, smI>>>(l, mlpb1 + (size_t)l * HID, mlpb2 + (size_t)l * HID);
        k_nodeL<<<NN / 64, 256, NSM_TOTAL>>>(l, l == NLAY - 1,
                                             lin2b + (size_t)l * HID,
                                             linb + (size_t)l * HID, outp);
    }
}

// round 15
// speedup vs baseline: 1.5750x; 1.2241x over previous
#include <cuda_runtime.h>
#include <cuda_fp16.h>
#include <math.h>

// ---------------- problem constants ----------------
#define NN    8192
#define EE    262144
#define HID   128
#define NRBF  50
#define K1    64
#define NLAY  6
#define PR    72           // smem pitch (fp16) for rbf / W1^T
#define PT    136          // smem pitch (fp16) for T / W2^T / node tiles
#define PG    132          // smem pitch (fp16) for F / Hstage in edge kernel
#define NSLOT 20

typedef __half  h16;
typedef __half2 h162;

// ---------------- device scratch ----------------
__device__ __align__(16) h16 g_rbf[(size_t)EE * K1];
__device__ __align__(16) h16 g_w1t[NLAY * HID * K1];
__device__ __align__(16) h16 g_w2t[NLAY * HID * HID];
__device__ __align__(16) h16 g_npt[HID * K1];
__device__ __align__(16) h16 g_nwt[NSLOT * HID * HID];
__device__ __align__(16) h16 g_h16 [NN * HID];
__device__ __align__(16) h16 g_nex16[NN * HID];
__device__ float g_cut[EE];
__device__ float g_cutm[EE];
__device__ int   g_srow[EE];
__device__ int   g_sdst[EE];
__device__ int   g_perm[EE];
__device__ int   g_cnt[NN];
__device__ int   g_offm[NN];
__device__ float g_x  [NN * HID];
__device__ float g_agg[NN * HID];

// ---------------- small helper kernels ----------------
__global__ void k_zero_cnt() {
    int i = blockIdx.x * blockDim.x + threadIdx.x;
    if (i < NN) g_cnt[i] = 0;
}

__global__ void k_hist(const int* __restrict__ ei) {
    int e = blockIdx.x * blockDim.x + threadIdx.x;
    if (e < EE) atomicAdd(&g_cnt[ei[EE + e]], 1);
}

__global__ void k_scan() {
    __shared__ int part[1024];
    int t = threadIdx.x;
    int base = t * 8;
    int loc[8];
    int s = 0;
#pragma unroll
    for (int i = 0; i < 8; i++) { loc[i] = s; s += g_cnt[base + i]; }
    part[t] = s;
    __syncthreads();
    int val = s;
    for (int off = 1; off < 1024; off <<= 1) {
        int v = (t >= off) ? part[t - off] : 0;
        __syncthreads();
        val += v;
        part[t] = val;
        __syncthreads();
    }
    int pre = (t == 0) ? 0 : part[t - 1];
#pragma unroll
    for (int i = 0; i < 8; i++) g_offm[base + i] = pre + loc[i];
}

__global__ void k_place(const int* __restrict__ ei) {
    int e = blockIdx.x * blockDim.x + threadIdx.x;
    if (e < EE) {
        int c = ei[EE + e];
        int p = atomicAdd(&g_offm[c], 1);
        g_perm[p] = e;
    }
}

__global__ void k_build(const int* __restrict__ ei, const float* __restrict__ ew,
                        const float* __restrict__ means, const float* __restrict__ betas) {
    int warp = (blockIdx.x * blockDim.x + threadIdx.x) >> 5;
    int lane = threadIdx.x & 31;
    if (warp >= EE) return;
    int e = g_perm[warp];
    int r = ei[e];
    int c = ei[EE + e];
    float d = ew[e];
    float cut = 0.5f * (cosf(d * 0.628318530717958647692f) + 1.0f);
    if (!(d < 5.0f)) cut = 0.f;
    float ex = __expf(-d);
    size_t ro = (size_t)warp * K1;
    {
        float m = means[lane], b = betas[lane];
        float v = ex - m;
        g_rbf[ro + lane] = __float2half_rn(cut * __expf(-b * v * v));
    }
    int k2 = lane + 32;
    float val2 = 0.f;
    if (k2 < NRBF) {
        float m = means[k2], b = betas[k2];
        float v = ex - m;
        val2 = cut * __expf(-b * v * v);
    }
    g_rbf[ro + k2] = __float2half_rn(val2);
    if (lane == 0) {
        g_cut[warp]  = cut;
        g_cutm[warp] = (r != c) ? cut : 0.f;
        g_srow[warp] = r;
        g_sdst[warp] = c;
    }
}

__global__ void k_gather(const int* __restrict__ z, const float* __restrict__ emb,
                         const float* __restrict__ neemb) {
    int i = blockIdx.x * blockDim.x + threadIdx.x;
    if (i >= NN * HID) return;
    int n = i >> 7, c = i & 127;
    int zi = z[n];
    g_x[i]     = emb[zi * HID + c];
    g_nex16[i] = __float2half_rn(neemb[zi * HID + c]);
    g_agg[i]   = 0.f;
}

// weight prep (single fp16, transposed)
__global__ void k_wprep1(const float* __restrict__ w, int mode, int layers) {
    int i = blockIdx.x * blockDim.x + threadIdx.x;
    if (i >= layers * HID * K1) return;
    int k = i & (K1 - 1);
    int n = (i >> 6) & (HID - 1);
    int l = i >> 13;
    float v = (k < NRBF) ? w[((size_t)l * NRBF + k) * HID + n] : 0.f;
    if (mode == 0) g_w1t[i] = __float2half_rn(v);
    else           g_npt[i] = __float2half_rn(v);
}

__global__ void k_wprep2(const float* __restrict__ w) {
    int i = blockIdx.x * blockDim.x + threadIdx.x;
    if (i >= NLAY * HID * HID) return;
    int k = i & (HID - 1);
    int n = (i >> 7) & (HID - 1);
    int l = i >> 14;
    g_w2t[i] = __float2half_rn(w[((size_t)l * HID + k) * HID + n]);
}

__global__ void k_wprepAll(const float* __restrict__ necatw, const float* __restrict__ lin1w,
                           const float* __restrict__ lin2w, const float* __restrict__ linw) {
    int slot = blockIdx.x >> 6;
    int i = (blockIdx.x & 63) * 256 + threadIdx.x;
    const float* src;
    if (slot < 2)       src = necatw + (size_t)slot * HID * HID;
    else if (slot < 8)  src = lin1w + (size_t)(slot - 2) * HID * HID;
    else if (slot < 14) src = lin2w + (size_t)(slot - 8) * HID * HID;
    else                src = linw  + (size_t)(slot - 14) * HID * HID;
    int k = i & (HID - 1);
    int n = i >> 7;
    g_nwt[(size_t)slot * HID * HID + i] = __float2half_rn(src[k * HID + n]);
}

// ---------------- warp-MMA helpers (fp16) ----------------
__device__ __forceinline__ void mma16816(float c[4], const unsigned a[4], const unsigned b[2]) {
    asm volatile(
        "mma.sync.aligned.m16n8k16.row.col.f32.f16.f16.f32 "
        "{%0,%1,%2,%3}, {%4,%5,%6,%7}, {%8,%9}, {%0,%1,%2,%3};\n"
        : "+f"(c[0]), "+f"(c[1]), "+f"(c[2]), "+f"(c[3])
        : "r"(a[0]), "r"(a[1]), "r"(a[2]), "r"(a[3]), "r"(b[0]), "r"(b[1]));
}

__device__ __forceinline__ void ldsm4(unsigned r[4], unsigned addr) {
    asm volatile("ldmatrix.sync.aligned.m8n8.x4.shared.b16 {%0,%1,%2,%3}, [%4];"
        : "=r"(r[0]), "=r"(r[1]), "=r"(r[2]), "=r"(r[3]) : "r"(addr));
}

__device__ __forceinline__ unsigned a_addr(unsigned base, int m0, int PB, int lane) {
    int sel = lane >> 3, li = lane & 7;
    return base + (m0 + li + (sel & 1) * 8) * PB + ((sel >> 1) * 8) * 2;
}
__device__ __forceinline__ unsigned b_addr(unsigned base, int n0, int PB, int lane) {
    int sel = lane >> 3, li = lane & 7;
    return base + (n0 + li + (sel >> 1) * 8) * PB + ((sel & 1) * 8) * 2;
}

// 32x32 warp GEMM: acc += A*B; both single fp16
template <int KSTEPS, int PB>
__device__ __forceinline__ void wgemm1(unsigned aA, unsigned bB, float acc[2][4][4]) {
#pragma unroll
    for (int ks = 0; ks < KSTEPS; ks++) {
        unsigned off = ks * 32;
        unsigned a0[4], a1[4], b0[4], b1[4];
        ldsm4(a0, aA + off);
        ldsm4(a1, aA + 16 * PB + off);
        ldsm4(b0, bB + off);
        ldsm4(b1, bB + 16 * PB + off);
#pragma unroll
        for (int nt = 0; nt < 4; nt++) {
            const unsigned* bp = (nt < 2) ? (b0 + 2 * nt) : (b1 + 2 * (nt - 2));
            mma16816(acc[0][nt], a0, bp);
            mma16816(acc[1][nt], a1, bp);
        }
    }
}

// ---------------- cp.async helpers ----------------
__device__ __forceinline__ void cpa16(unsigned saddr, const void* gaddr) {
    asm volatile("cp.async.ca.shared.global [%0], [%1], 16;" :: "r"(saddr), "l"(gaddr));
}
__device__ __forceinline__ void cpa8(unsigned saddr, const void* gaddr) {
    asm volatile("cp.async.ca.shared.global [%0], [%1], 8;" :: "r"(saddr), "l"(gaddr));
}
__device__ __forceinline__ void cpa_commit() { asm volatile("cp.async.commit_group;"); }
__device__ __forceinline__ void cpa_wait0()  { asm volatile("cp.async.wait_group 0;"); }
__device__ __forceinline__ void cpa_wait1()  { asm volatile("cp.async.wait_group 1;"); }

__device__ __forceinline__ float fsilu(float x) {
    return __fdividef(x, 1.f + __expf(-x));
}

// ---------------- fused edge MLP + segmented aggregation (persistent) --------
// interaction smem: T[0,34816) W2[34816,+34816) rbf[69632,+18432) W1[88064,+18432)
//   H16[106496,+33792) F16[140288,+33792) misc[174080,+4096) = 178176 (occ 1)
// NE smem: F16[0,33792) rbf[33792,+18432) W1[52224,+18432) H16[70656,+33792)
//   misc[104448,+4096) = 108544 (occ 2; launch 296 blocks)
template <int NE>
__global__ void __launch_bounds__(512, 1)
k_edge(int layer, const float* __restrict__ b1g, const float* __restrict__ b2g) {
    extern __shared__ __align__(16) char smref[];
    const int OFF_T    = 0;                  // interaction only
    const int OFF_W2   = 34816;
    const int OFF_R    = NE ? 33792 : 69632;
    const int OFF_W1   = OFF_R + 18432;
    const int OFF_H    = NE ? 70656 : 106496;
    const int OFF_F    = NE ? 0 : 140288;
    const int OFF_MISC = NE ? 104448 : 174080;
    const int OFF_CUT  = OFF_MISC;          // [2][128] f32
    const int OFF_ROW  = OFF_MISC + 1024;   // [2][128] i32
    const int OFF_DST  = OFF_MISC + 2048;   // [2][128] i32
    const int OFF_B1   = OFF_MISC + 3072;
    const int OFF_B2   = OFF_MISC + 3584;

    h16*  sT   = (h16*)(smref + OFF_T);
    h16*  sF16 = (h16*)(smref + OFF_F);
    h16*  sH16 = (h16*)(smref + OFF_H);
    float* sB1 = (float*)(smref + OFF_B1);
    float* sB2 = (float*)(smref + OFF_B2);

    int tid = threadIdx.x;
    unsigned sbase = (unsigned)__cvta_generic_to_shared(smref);

    const long NT = EE / 128;
    long tile = blockIdx.x;
    int buf = 0;

    // issue tile-0 rbf + metadata copy
    if (tile < NT) {
        long ebase = tile * 128;
        for (int c = tid; c < 1024; c += 512) {
            int r = c >> 3, ch = c & 7;
            cpa16(sbase + OFF_R + r * (PR * 2) + ch * 16, &g_rbf[(ebase + r) * K1 + ch * 8]);
        }
        if (tid < 32) {
            const float* cs = NE ? g_cutm : g_cut;
            cpa16(sbase + OFF_CUT + tid * 16, cs + ebase + tid * 4);
        } else if (tid < 64) {
            int t = tid - 32;
            cpa16(sbase + OFF_ROW + t * 16, g_srow + ebase + t * 4);
        } else if (tid < 96) {
            int t = tid - 64;
            cpa16(sbase + OFF_DST + t * 16, g_sdst + ebase + t * 4);
        }
    }
    cpa_commit();

    // ---- stage weights once (single fp16) ----
    {
        const unsigned* gw = (const unsigned*)(NE ? g_npt : (g_w1t + (size_t)layer * HID * K1));
        unsigned* sw = (unsigned*)(smref + OFF_W1);
        for (int i = tid; i < 128 * 32; i += 512) {
            int r = i >> 5, wd = i & 31;
            sw[r * (PR / 2) + wd] = gw[i];
        }
    }
    if (!NE) {
        const unsigned* gw = (const unsigned*)(g_w2t + (size_t)layer * HID * HID);
        unsigned* sw = (unsigned*)(smref + OFF_W2);
        for (int i = tid; i < 128 * 64; i += 512) {
            int r = i >> 6, wd = i & 63;
            sw[r * (PT / 2) + wd] = gw[i];
        }
    }
    if (tid < 128) {
        sB1[tid] = b1g[tid];
        sB2[tid] = NE ? 0.f : b2g[tid];
    }

    int w = tid >> 5, lane = tid & 31;
    int m0 = (w & 3) * 32, n0 = (w >> 2) * 32;
    int g = lane >> 2, tc = lane & 3;

    unsigned g1a = a_addr(sbase + OFF_R,  m0, PR * 2, lane);
    unsigned g1b = b_addr(sbase + OFF_W1, n0, PR * 2, lane);
    unsigned g2a = a_addr(sbase + OFF_T,  m0, PT * 2, lane);
    unsigned g2b = b_addr(sbase + OFF_W2, n0, PT * 2, lane);

    const h16* hsrc = NE ? g_nex16 : g_h16;

    for (; tile < NT; tile += gridDim.x, buf ^= 1) {
        cpa_wait0();
        __syncthreads();   // rbf + meta[buf] ready; prev aggregation done (H/F free)

        float* sCut = (float*)(smref + OFF_CUT + buf * 512);
        int*   sRow = (int*)(smref + OFF_ROW + buf * 512);
        int*   sDst = (int*)(smref + OFF_DST + buf * 512);

        // ---- stage gathered h rows (fp16) — 8B cp.async, pitch 264B ----
        for (int i = tid; i < 4096; i += 512) {
            int e = i >> 5, ch = i & 31;
            cpa8(sbase + OFF_H + e * (PG * 2) + ch * 8,
                 hsrc + (long)sRow[e] * HID + ch * 4);
        }
        cpa_commit();      // group A (Hstage)

        // ---- GEMM1: rbf[128,64] @ W1[64,128] ----
        {
            float acc[2][4][4];
#pragma unroll
            for (int a = 0; a < 2; a++)
#pragma unroll
                for (int b = 0; b < 4; b++)
#pragma unroll
                    for (int c = 0; c < 4; c++) acc[a][b][c] = 0.f;
            wgemm1<K1 / 16, PR * 2>(g1a, g1b, acc);

            if (NE) {
#pragma unroll
                for (int mt = 0; mt < 2; mt++) {
                    int ra = m0 + mt * 16 + g, rb2 = ra + 8;
                    float cua = sCut[ra], cub = sCut[rb2];
#pragma unroll
                    for (int nt = 0; nt < 4; nt++) {
                        int col = n0 + nt * 8 + 2 * tc;
                        *(h162*)&sF16[ra * PG + col] = __floats2half2_rn(
                            (acc[mt][nt][0] + sB1[col]) * cua,
                            (acc[mt][nt][1] + sB1[col + 1]) * cua);
                        *(h162*)&sF16[rb2 * PG + col] = __floats2half2_rn(
                            (acc[mt][nt][2] + sB1[col]) * cub,
                            (acc[mt][nt][3] + sB1[col + 1]) * cub);
                    }
                }
            } else {
#pragma unroll
                for (int mt = 0; mt < 2; mt++) {
                    int ra = m0 + mt * 16 + g, rb2 = ra + 8;
#pragma unroll
                    for (int nt = 0; nt < 4; nt++) {
                        int col = n0 + nt * 8 + 2 * tc;
                        float x0 = fsilu(acc[mt][nt][0] + sB1[col]);
                        float x1 = fsilu(acc[mt][nt][1] + sB1[col + 1]);
                        float x2 = fsilu(acc[mt][nt][2] + sB1[col]);
                        float x3 = fsilu(acc[mt][nt][3] + sB1[col + 1]);
                        *(h162*)&sT[ra * PT + col]  = __floats2half2_rn(x0, x1);
                        *(h162*)&sT[rb2 * PT + col] = __floats2half2_rn(x2, x3);
                    }
                }
            }
        }
        __syncthreads();   // rbf dead; T (or F) visible

        // ---- issue next tile's rbf + metadata (group B) ----
        {
            long nxt = tile + gridDim.x;
            if (nxt < NT) {
                long ebase = nxt * 128;
                int nb = buf ^ 1;
                for (int c = tid; c < 1024; c += 512) {
                    int r = c >> 3, ch = c & 7;
                    cpa16(sbase + OFF_R + r * (PR * 2) + ch * 16,
                          &g_rbf[(ebase + r) * K1 + ch * 8]);
                }
                if (tid < 32) {
                    const float* cs = NE ? g_cutm : g_cut;
                    cpa16(sbase + OFF_CUT + nb * 512 + tid * 16, cs + ebase + tid * 4);
                } else if (tid < 64) {
                    int t = tid - 32;
                    cpa16(sbase + OFF_ROW + nb * 512 + t * 16, g_srow + ebase + t * 4);
                } else if (tid < 96) {
                    int t = tid - 64;
                    cpa16(sbase + OFF_DST + nb * 512 + t * 16, g_sdst + ebase + t * 4);
                }
            }
            cpa_commit();
        }

        // ---- GEMM2 (interaction only): T @ W2 -> F (separate region) ----
        if (!NE) {
            float acc[2][4][4];
#pragma unroll
            for (int a = 0; a < 2; a++)
#pragma unroll
                for (int b = 0; b < 4; b++)
#pragma unroll
                    for (int c = 0; c < 4; c++) acc[a][b][c] = 0.f;
            wgemm1<HID / 16, PT * 2>(g2a, g2b, acc);
#pragma unroll
            for (int mt = 0; mt < 2; mt++) {
                int ra = m0 + mt * 16 + g, rb2 = ra + 8;
                float cua = sCut[ra], cub = sCut[rb2];
#pragma unroll
                for (int nt = 0; nt < 4; nt++) {
                    int col = n0 + nt * 8 + 2 * tc;
                    *(h162*)&sF16[ra * PG + col] = __floats2half2_rn(
                        (acc[mt][nt][0] + sB2[col]) * cua,
                        (acc[mt][nt][1] + sB2[col + 1]) * cua);
                    *(h162*)&sF16[rb2 * PG + col] = __floats2half2_rn(
                        (acc[mt][nt][2] + sB2[col]) * cub,
                        (acc[mt][nt][3] + sB2[col + 1]) * cub);
                }
            }
        }
        __syncthreads();   // F visible

        // ---- wait for Hstage (group B may stay in flight), aggregate ----
        cpa_wait1();

        int grp = tid >> 6;
        int f2 = tid & 63;
        int c0 = 2 * f2;
        int e0 = grp * 16;
        float a0 = 0.f, a1 = 0.f;
        int cur = sDst[e0];
#pragma unroll 4
        for (int j = 0; j < 16; j++) {
            int e = e0 + j;
            int dd = sDst[e];
            if (dd != cur) {
                atomicAdd(&g_agg[(long)cur * HID + c0], a0);
                atomicAdd(&g_agg[(long)cur * HID + c0 + 1], a1);
                a0 = a1 = 0.f;
                cur = dd;
            }
            float2 hf = __half22float2(*(const h162*)&sH16[e * PG + c0]);
            float2 ff = __half22float2(*(const h162*)&sF16[e * PG + c0]);
            a0 = fmaf(hf.x, ff.x, a0);
            a1 = fmaf(hf.y, ff.y, a1);
        }
        atomicAdd(&g_agg[(long)cur * HID + c0], a0);
        atomicAdd(&g_agg[(long)cur * HID + c0 + 1], a1);
    }
}

// ---------------- node-kernel shared pieces ----------------
#define NA_BYTES  (64 * PT * 2)     // 17408
#define NW_BYTES  (HID * PT * 2)    // 34816
#define NOFF_A    0
#define NOFF_WA   NA_BYTES
#define NOFF_WB   (NOFF_WA + NW_BYTES)
#define NOFF_H    (NOFF_WB + NW_BYTES)
#define NOFF_B    (NOFF_H + NA_BYTES)
#define NSM_TOTAL (NOFF_B + 1024)   // 105472

__device__ __forceinline__ void stageA_f16(char* smref, int off, const float* src,
                                           int rb, int tid) {
    h16* dst = (h16*)(smref + off);
    for (int i = tid; i < 64 * HID; i += 256) {
        int r = i >> 7, k = i & 127;
        dst[r * PT + k] = __float2half_rn(src[(long)(rb + r) * HID + k]);
    }
}

__device__ __forceinline__ void stageW(char* smref, int off, int slot, int tid) {
    const unsigned* gw = (const unsigned*)(g_nwt + (size_t)slot * HID * HID);
    unsigned* sw = (unsigned*)(smref + off);
    for (int i = tid; i < 128 * 64; i += 256) {
        int r = i >> 6, wd = i & 63;
        sw[r * (PT / 2) + wd] = gw[i];
    }
}

// ---------------- NE node kernel: x = x@Wtop + agg@Wbot + b; h = x@lin1[0] ----
__global__ void __launch_bounds__(256, 1)
k_nodeNE(const float* __restrict__ necatb) {
    extern __shared__ __align__(16) char smref[];
    float* sBa = (float*)(smref + NOFF_B);

    int tid = threadIdx.x;
    int rb = blockIdx.x * 64;
    unsigned sbase = (unsigned)__cvta_generic_to_shared(smref);

    stageA_f16(smref, NOFF_A, g_x, rb, tid);
    stageW(smref, NOFF_WA, 0, tid);
    stageW(smref, NOFF_WB, 1, tid);
    if (tid < 128) sBa[tid] = necatb[tid];
    __syncthreads();

    int w = tid >> 5, lane = tid & 31;
    int m0 = (w & 1) * 32, n0 = (w >> 1) * 32;
    int g = lane >> 2, tc = lane & 3;

    float acc[2][4][4];
#pragma unroll
    for (int a = 0; a < 2; a++)
#pragma unroll
        for (int b = 0; b < 4; b++)
#pragma unroll
            for (int c = 0; c < 4; c++) acc[a][b][c] = 0.f;

    {
        unsigned aA = a_addr(sbase + NOFF_A, m0, PT * 2, lane);
        unsigned bB = b_addr(sbase + NOFF_WA, n0, PT * 2, lane);
        wgemm1<HID / 16, PT * 2>(aA, bB, acc);
    }
    __syncthreads();

    stageA_f16(smref, NOFF_A, g_agg, rb, tid);
    stageW(smref, NOFF_WA, 2, tid);
    __syncthreads();

    {
        float4* za = (float4*)(g_agg + (long)rb * HID);
        for (int i = tid; i < 64 * HID / 4; i += 256) za[i] = make_float4(0.f, 0.f, 0.f, 0.f);
    }

    {
        unsigned aA = a_addr(sbase + NOFF_A, m0, PT * 2, lane);
        unsigned bB = b_addr(sbase + NOFF_WB, n0, PT * 2, lane);
        wgemm1<HID / 16, PT * 2>(aA, bB, acc);

        h16* xh = (h16*)(smref + NOFF_H);
#pragma unroll
        for (int mt = 0; mt < 2; mt++) {
#pragma unroll
            for (int dr = 0; dr < 2; dr++) {
                int r = m0 + mt * 16 + g + dr * 8;
                long ro = (long)(rb + r) * HID;
#pragma unroll
                for (int nt = 0; nt < 4; nt++) {
                    int col = n0 + nt * 8 + 2 * tc;
                    float v0 = acc[mt][nt][2 * dr]     + sBa[col];
                    float v1 = acc[mt][nt][2 * dr + 1] + sBa[col + 1];
                    *(float2*)&g_x[ro + col] = make_float2(v0, v1);
                    *(h162*)&xh[r * PT + col] = __floats2half2_rn(v0, v1);
                }
            }
        }
    }
    __syncthreads();

    // GEMM C: h = x @ lin1[0] -> g_h16
    {
        float acc2[2][4][4];
#pragma unroll
        for (int a = 0; a < 2; a++)
#pragma unroll
            for (int b = 0; b < 4; b++)
#pragma unroll
                for (int c = 0; c < 4; c++) acc2[a][b][c] = 0.f;
        unsigned aA = a_addr(sbase + NOFF_H, m0, PT * 2, lane);
        unsigned bB = b_addr(sbase + NOFF_WA, n0, PT * 2, lane);
        wgemm1<HID / 16, PT * 2>(aA, bB, acc2);
#pragma unroll
        for (int mt = 0; mt < 2; mt++) {
#pragma unroll
            for (int dr = 0; dr < 2; dr++) {
                int r = m0 + mt * 16 + g + dr * 8;
                long ro = (long)(rb + r) * HID;
#pragma unroll
                for (int nt = 0; nt < 4; nt++) {
                    int col = n0 + nt * 8 + 2 * tc;
                    *(h162*)&g_h16[ro + col] =
                        __floats2half2_rn(acc2[mt][nt][2 * dr], acc2[mt][nt][2 * dr + 1]);
                }
            }
        }
    }
}

// ---------------- layer node kernel ----------------
__global__ void __launch_bounds__(256, 1)
k_nodeL(int l, int last, const float* __restrict__ b2g, const float* __restrict__ b3g,
        float* dout) {
    extern __shared__ __align__(16) char smref[];
    float* sB2 = (float*)(smref + NOFF_B);
    float* sB3 = sB2 + 128;

    int tid = threadIdx.x;
    int rb = blockIdx.x * 64;
    unsigned sbase = (unsigned)__cvta_generic_to_shared(smref);

    stageA_f16(smref, NOFF_A, g_agg, rb, tid);
    stageW(smref, NOFF_WA, 8 + l, tid);
    stageW(smref, NOFF_WB, 14 + l, tid);
    if (tid < 128) { sB2[tid] = b2g[tid]; sB3[tid] = b3g[tid]; }
    __syncthreads();

    int w = tid >> 5, lane = tid & 31;
    int m0 = (w & 1) * 32, n0 = (w >> 1) * 32;
    int g = lane >> 2, tc = lane & 3;

    // GEMM A: H = silu(agg @ lin2 + b2)
    {
        float acc[2][4][4];
#pragma unroll
        for (int a = 0; a < 2; a++)
#pragma unroll
            for (int b = 0; b < 4; b++)
#pragma unroll
                for (int c = 0; c < 4; c++) acc[a][b][c] = 0.f;
        unsigned aA = a_addr(sbase + NOFF_A, m0, PT * 2, lane);
        unsigned bB = b_addr(sbase + NOFF_WA, n0, PT * 2, lane);
        wgemm1<HID / 16, PT * 2>(aA, bB, acc);

        h16* sHn = (h16*)(smref + NOFF_H);
#pragma unroll
        for (int mt = 0; mt < 2; mt++) {
            int ra = m0 + mt * 16 + g, rb2 = ra + 8;
#pragma unroll
            for (int nt = 0; nt < 4; nt++) {
                int col = n0 + nt * 8 + 2 * tc;
                float x0 = fsilu(acc[mt][nt][0] + sB2[col]);
                float x1 = fsilu(acc[mt][nt][1] + sB2[col + 1]);
                float x2 = fsilu(acc[mt][nt][2] + sB2[col]);
                float x3 = fsilu(acc[mt][nt][3] + sB2[col + 1]);
                *(h162*)&sHn[ra * PT + col]  = __floats2half2_rn(x0, x1);
                *(h162*)&sHn[rb2 * PT + col] = __floats2half2_rn(x2, x3);
            }
        }
    }
    __syncthreads();

    if (!last) {
        stageW(smref, NOFF_WA, 2 + (l + 1), tid);
        float4* za = (float4*)(g_agg + (long)rb * HID);
        for (int i = tid; i < 64 * HID / 4; i += 256) za[i] = make_float4(0.f, 0.f, 0.f, 0.f);
    }

    // GEMM B: x = H @ lin + b3 + x_old
    {
        float acc[2][4][4];
#pragma unroll
        for (int a = 0; a < 2; a++)
#pragma unroll
            for (int b = 0; b < 4; b++)
#pragma unroll
                for (int c = 0; c < 4; c++) acc[a][b][c] = 0.f;
        unsigned aA = a_addr(sbase + NOFF_H, m0, PT * 2, lane);
        unsigned bB = b_addr(sbase + NOFF_WB, n0, PT * 2, lane);
        wgemm1<HID / 16, PT * 2>(aA, bB, acc);

        float* out = last ? dout : g_x;
        h16* xh = (h16*)(smref + NOFF_A);
#pragma unroll
        for (int mt = 0; mt < 2; mt++) {
#pragma unroll
            for (int dr = 0; dr < 2; dr++) {
                int r = m0 + mt * 16 + g + dr * 8;
                long ro = (long)(rb + r) * HID;
#pragma unroll
                for (int nt = 0; nt < 4; nt++) {
                    int col = n0 + nt * 8 + 2 * tc;
                    float v0 = acc[mt][nt][2 * dr]     + sB3[col] + g_x[ro + col];
                    float v1 = acc[mt][nt][2 * dr + 1] + sB3[col + 1] + g_x[ro + col + 1];
                    *(float2*)&out[ro + col] = make_float2(v0, v1);
                    if (!last)
                        *(h162*)&xh[r * PT + col] = __floats2half2_rn(v0, v1);
                }
            }
        }
    }
    if (last) return;
    __syncthreads();

    // GEMM C: h = x @ lin1[l+1] -> g_h16
    {
        float acc[2][4][4];
#pragma unroll
        for (int a = 0; a < 2; a++)
#pragma unroll
            for (int b = 0; b < 4; b++)
#pragma unroll
                for (int c = 0; c < 4; c++) acc[a][b][c] = 0.f;
        unsigned aA = a_addr(sbase + NOFF_A, m0, PT * 2, lane);
        unsigned bB = b_addr(sbase + NOFF_WA, n0, PT * 2, lane);
        wgemm1<HID / 16, PT * 2>(aA, bB, acc);
#pragma unroll
        for (int mt = 0; mt < 2; mt++) {
#pragma unroll
            for (int dr = 0; dr < 2; dr++) {
                int r = m0 + mt * 16 + g + dr * 8;
                long ro = (long)(rb + r) * HID;
#pragma unroll
                for (int nt = 0; nt < 4; nt++) {
                    int col = n0 + nt * 8 + 2 * tc;
                    *(h162*)&g_h16[ro + col] =
                        __floats2half2_rn(acc[mt][nt][2 * dr], acc[mt][nt][2 * dr + 1]);
                }
            }
        }
    }
}

// ---------------- launch ----------------
extern "C" void kernel_launch(void* const* d_in, const int* in_sizes, int n_in,
                              void* d_out, int out_size) {
    const int*   z       = (const int*)d_in[0];
    const int*   ei      = (const int*)d_in[1];
    const float* ew      = (const float*)d_in[2];
    const float* emb     = (const float*)d_in[3];
    const float* neemb   = (const float*)d_in[4];
    const float* neprojw = (const float*)d_in[5];
    const float* neprojb = (const float*)d_in[6];
    const float* necatw  = (const float*)d_in[7];
    const float* necatb  = (const float*)d_in[8];
    const float* means   = (const float*)d_in[9];
    const float* betas   = (const float*)d_in[10];
    const float* mlpw1   = (const float*)d_in[11];
    const float* mlpb1   = (const float*)d_in[12];
    const float* mlpw2   = (const float*)d_in[13];
    const float* mlpb2   = (const float*)d_in[14];
    const float* lin1w   = (const float*)d_in[15];
    const float* lin2w   = (const float*)d_in[16];
    const float* lin2b   = (const float*)d_in[17];
    const float* linw    = (const float*)d_in[18];
    const float* linb    = (const float*)d_in[19];
    float* outp = (float*)d_out;

    const int smI = 174080 + 4096;   // 178176  (occupancy 1)
    const int smN = 104448 + 4096;   // 108544  (occupancy 2)

    cudaFuncSetAttribute(k_edge<0>, cudaFuncAttributeMaxDynamicSharedMemorySize, smI);
    cudaFuncSetAttribute(k_edge<1>, cudaFuncAttributeMaxDynamicSharedMemorySize, smN);
    cudaFuncSetAttribute(k_nodeNE,  cudaFuncAttributeMaxDynamicSharedMemorySize, NSM_TOTAL);
    cudaFuncSetAttribute(k_nodeL,   cudaFuncAttributeMaxDynamicSharedMemorySize, NSM_TOTAL);

    // ---- sort edges by destination + precompute per-edge data ----
    k_zero_cnt<<<NN / 256, 256>>>();
    k_hist<<<EE / 256, 256>>>(ei);
    k_scan<<<1, 1024>>>();
    k_place<<<EE / 256, 256>>>(ei);
    k_build<<<EE / 8, 256>>>(ei, ew, means, betas);
    k_gather<<<NN * HID / 256, 256>>>(z, emb, neemb);

    // ---- weight prep ----
    k_wprep1<<<(NLAY * HID * K1 + 255) / 256, 256>>>(mlpw1, 0, NLAY);
    k_wprep1<<<(HID * K1 + 255) / 256, 256>>>(neprojw, 1, 1);
    k_wprep2<<<(NLAY * HID * HID + 255) / 256, 256>>>(mlpw2);
    k_wprepAll<<<NSLOT * 64, 256>>>(necatw, lin1w, lin2w, linw);

    // ---- NeighborEmbedding + initial lin1 ----
    k_edge<1><<<296, 512, smN>>>(0, neprojb, nullptr);   // occ 2
    k_nodeNE<<<NN / 64, 256, NSM_TOTAL>>>(necatb);

    // ---- interaction layers ----
    for (int l = 0; l < NLAY; l++) {
        k_edge<0><<<148, 512, smI>>>(l, mlpb1 + (size_t)l * HID, mlpb2 + (size_t)l * HID);
        k_nodeL<<<NN / 64, 256, NSM_TOTAL>>>(l, l == NLAY - 1,
                                             lin2b + (size_t)l * HID,
                                             linb + (size_t)l * HID, outp);
    }
}